// round 1
// baseline (speedup 1.0000x reference)
#include <cuda_runtime.h>
#include <math.h>
#include <stdint.h>

// Problem constants
#define Bsz 2
#define Sl  2048
#define Dm  1024
#define Hn  16
#define HKn 4
#define HDn 64
#define DKn 64
#define DVn 64
#define NCH 32          // S / CHUNK
#define MS  (Bsz*Sl)    // 4096 rows

// Scratch (global device arrays; no runtime allocation allowed)
__device__ float g_q[Bsz*Sl*Hn*HDn];     // 16 MB
__device__ float g_k[Bsz*Sl*HKn*HDn];    // 4 MB
__device__ float g_v[Bsz*Sl*HKn*HDn];    // 4 MB
__device__ float g_attn[Bsz*Sl*Hn*HDn];  // 16 MB
__device__ float g_z[Bsz*Sl*DKn];        // 2 MB
__device__ float g_mem[Bsz*Sl*DVn];      // 2 MB

// ---------------------------------------------------------------------------
// Generic tiled SGEMM: C[M,N] = A[M,K] @ B[K,N], row-major.
// 64x64 tile, BK=16, 256 threads, 4x4 microtile per thread.
// Requires M%64==0, N%64==0, K%16==0 (true for all our shapes).
// ---------------------------------------------------------------------------
__global__ void sgemm_kernel(const float* __restrict__ A, const float* __restrict__ B,
                             float* __restrict__ C, int M, int N, int K) {
    __shared__ float As[16][64];
    __shared__ float Bs[16][64];
    int tid = threadIdx.x;
    int tx = tid & 15, ty = tid >> 4;
    int row0 = blockIdx.y * 64, col0 = blockIdx.x * 64;
    float acc[4][4] = {};
    for (int k0 = 0; k0 < K; k0 += 16) {
        #pragma unroll
        for (int i = 0; i < 4; i++) {
            int idx = tid + i * 256;                 // 0..1023
            int m  = idx >> 4, kk = idx & 15;
            As[kk][m] = A[(size_t)(row0 + m) * K + k0 + kk];
            int kb = idx >> 6, n = idx & 63;
            Bs[kb][n] = B[(size_t)(k0 + kb) * N + col0 + n];
        }
        __syncthreads();
        #pragma unroll
        for (int kk = 0; kk < 16; kk++) {
            float a[4], b[4];
            #pragma unroll
            for (int i = 0; i < 4; i++) a[i] = As[kk][ty * 4 + i];
            #pragma unroll
            for (int j = 0; j < 4; j++) b[j] = Bs[kk][tx * 4 + j];
            #pragma unroll
            for (int i = 0; i < 4; i++)
                #pragma unroll
                for (int j = 0; j < 4; j++)
                    acc[i][j] += a[i] * b[j];
        }
        __syncthreads();
    }
    #pragma unroll
    for (int i = 0; i < 4; i++)
        #pragma unroll
        for (int j = 0; j < 4; j++)
            C[(size_t)(row0 + ty * 4 + i) * N + col0 + tx * 4 + j] = acc[i][j];
}

// ---------------------------------------------------------------------------
// Fused final GEMM: C = A1[M,K1]@B1[K1,N] + A2[M,K2]@B2[K2,N]
// ---------------------------------------------------------------------------
__global__ void sgemm_dual_kernel(const float* __restrict__ A1, const float* __restrict__ B1, int K1,
                                  const float* __restrict__ A2, const float* __restrict__ B2, int K2,
                                  float* __restrict__ C, int N) {
    __shared__ float As[16][64];
    __shared__ float Bs[16][64];
    int tid = threadIdx.x;
    int tx = tid & 15, ty = tid >> 4;
    int row0 = blockIdx.y * 64, col0 = blockIdx.x * 64;
    float acc[4][4] = {};
    #pragma unroll
    for (int phase = 0; phase < 2; phase++) {
        const float* A = phase ? A2 : A1;
        const float* Bm = phase ? B2 : B1;
        int K = phase ? K2 : K1;
        for (int k0 = 0; k0 < K; k0 += 16) {
            #pragma unroll
            for (int i = 0; i < 4; i++) {
                int idx = tid + i * 256;
                int m  = idx >> 4, kk = idx & 15;
                As[kk][m] = A[(size_t)(row0 + m) * K + k0 + kk];
                int kb = idx >> 6, n = idx & 63;
                Bs[kb][n] = Bm[(size_t)(k0 + kb) * N + col0 + n];
            }
            __syncthreads();
            #pragma unroll
            for (int kk = 0; kk < 16; kk++) {
                float a[4], b[4];
                #pragma unroll
                for (int i = 0; i < 4; i++) a[i] = As[kk][ty * 4 + i];
                #pragma unroll
                for (int j = 0; j < 4; j++) b[j] = Bs[kk][tx * 4 + j];
                #pragma unroll
                for (int i = 0; i < 4; i++)
                    #pragma unroll
                    for (int j = 0; j < 4; j++)
                        acc[i][j] += a[i] * b[j];
            }
            __syncthreads();
        }
    }
    #pragma unroll
    for (int i = 0; i < 4; i++)
        #pragma unroll
        for (int j = 0; j < 4; j++)
            C[(size_t)(row0 + ty * 4 + i) * N + col0 + tx * 4 + j] = acc[i][j];
}

// ---------------------------------------------------------------------------
// RoPE in place on [B, S, nheads, 64]. One thread per (b,s,h,pair j<32).
// out_j      = u_j*cos - u_{j+32}*sin
// out_{j+32} = u_{j+32}*cos + u_j*sin   (same freq for both halves)
// ---------------------------------------------------------------------------
__global__ void rope_kernel(float* __restrict__ t, int nheads) {
    int idx = blockIdx.x * blockDim.x + threadIdx.x;
    int total = Bsz * Sl * nheads * 32;
    if (idx >= total) return;
    int j = idx & 31;
    int h = (idx >> 5) % nheads;
    int s = ((idx >> 5) / nheads) % Sl;
    int b = idx / (32 * nheads * Sl);
    float inv = powf(500000.0f, -(float)(2 * j) / 64.0f);
    float ang = (float)s * inv;
    float c = cosf(ang), sn = sinf(ang);
    size_t base = ((size_t)(b * Sl + s) * nheads + h) * 64;
    float u1 = t[base + j], u2 = t[base + j + 32];
    t[base + j]      = u1 * c - u2 * sn;
    t[base + j + 32] = u2 * c + u1 * sn;
}

// ---------------------------------------------------------------------------
// Flash-style causal GQA attention.
// grid = (S/64 q-tiles, B*H). Block = 256 threads.
// Q tile 64x64 resident; KV tiles of 32 rows; online softmax in shared.
// ---------------------------------------------------------------------------
__global__ void attn_kernel(const float* __restrict__ q, const float* __restrict__ k,
                            const float* __restrict__ v, float* __restrict__ o) {
    __shared__ float qs[64][65];
    __shared__ float ks[32][65];
    __shared__ float vs[32][64];
    __shared__ float ss[64][33];
    __shared__ float mrow[64], lrow[64], frow[64];

    int qt = blockIdx.x;           // q tile (0..31)
    int bh = blockIdx.y;           // b*16 + h
    int b = bh >> 4, h = bh & 15;
    int kh = h >> 2;               // GQA: 4 q-heads per kv-head
    int tid = threadIdx.x;
    int tx = tid & 15, ty = tid >> 4;
    const float scale = 0.125f;    // 1/sqrt(64)

    // load + scale Q tile
    #pragma unroll
    for (int i = 0; i < 16; i++) {
        int idx = tid + i * 256;   // 0..4095
        int r = idx >> 6, d = idx & 63;
        qs[r][d] = q[((size_t)(b * Sl + qt * 64 + r) * Hn + h) * 64 + d] * scale;
    }
    if (tid < 64) { mrow[tid] = -1e30f; lrow[tid] = 0.f; }
    float acc[4][4] = {};
    int ktmax = 2 * qt + 1;        // kv tiles of 32 rows
    __syncthreads();

    for (int kt = 0; kt <= ktmax; kt++) {
        #pragma unroll
        for (int i = 0; i < 8; i++) {
            int idx = tid + i * 256;  // 0..2047
            int r = idx >> 6, d = idx & 63;
            size_t g = ((size_t)(b * Sl + kt * 32 + r) * HKn + kh) * 64 + d;
            ks[r][d] = k[g];
            vs[r][d] = v[g];
        }
        __syncthreads();

        // scores: rows ty*4..+3, cols tx*2..+1
        float sc[4][2] = {};
        #pragma unroll
        for (int d = 0; d < 64; d++) {
            float a0 = qs[ty*4+0][d], a1 = qs[ty*4+1][d];
            float a2 = qs[ty*4+2][d], a3 = qs[ty*4+3][d];
            float b0 = ks[tx*2+0][d], b1 = ks[tx*2+1][d];
            sc[0][0] += a0*b0; sc[0][1] += a0*b1;
            sc[1][0] += a1*b0; sc[1][1] += a1*b1;
            sc[2][0] += a2*b0; sc[2][1] += a2*b1;
            sc[3][0] += a3*b0; sc[3][1] += a3*b1;
        }
        if (kt >= 2 * qt) {  // diagonal tiles need causal mask
            #pragma unroll
            for (int i = 0; i < 4; i++)
                #pragma unroll
                for (int j = 0; j < 2; j++) {
                    int rg = qt * 64 + ty * 4 + i;
                    int cg = kt * 32 + tx * 2 + j;
                    if (cg > rg) sc[i][j] = -1e30f;
                }
        }
        #pragma unroll
        for (int i = 0; i < 4; i++)
            #pragma unroll
            for (int j = 0; j < 2; j++)
                ss[ty*4+i][tx*2+j] = sc[i][j];
        __syncthreads();

        // online softmax row update (one thread per row)
        if (tid < 64) {
            float m_old = mrow[tid];
            float mx = m_old;
            #pragma unroll
            for (int c = 0; c < 32; c++) mx = fmaxf(mx, ss[tid][c]);
            float sum = 0.f;
            #pragma unroll
            for (int c = 0; c < 32; c++) {
                float p = __expf(ss[tid][c] - mx);
                ss[tid][c] = p;
                sum += p;
            }
            float f = __expf(m_old - mx);
            frow[tid] = f;
            lrow[tid] = lrow[tid] * f + sum;
            mrow[tid] = mx;
        }
        __syncthreads();

        // rescale + P@V accumulate
        float f0 = frow[ty*4+0], f1 = frow[ty*4+1];
        float f2 = frow[ty*4+2], f3 = frow[ty*4+3];
        #pragma unroll
        for (int j = 0; j < 4; j++) {
            acc[0][j] *= f0; acc[1][j] *= f1; acc[2][j] *= f2; acc[3][j] *= f3;
        }
        #pragma unroll
        for (int c = 0; c < 32; c++) {
            float p0 = ss[ty*4+0][c], p1 = ss[ty*4+1][c];
            float p2 = ss[ty*4+2][c], p3 = ss[ty*4+3][c];
            float v0 = vs[c][tx*4+0], v1 = vs[c][tx*4+1];
            float v2 = vs[c][tx*4+2], v3 = vs[c][tx*4+3];
            acc[0][0] += p0*v0; acc[0][1] += p0*v1; acc[0][2] += p0*v2; acc[0][3] += p0*v3;
            acc[1][0] += p1*v0; acc[1][1] += p1*v1; acc[1][2] += p1*v2; acc[1][3] += p1*v3;
            acc[2][0] += p2*v0; acc[2][1] += p2*v1; acc[2][2] += p2*v2; acc[2][3] += p2*v3;
            acc[3][0] += p3*v0; acc[3][1] += p3*v1; acc[3][2] += p3*v2; acc[3][3] += p3*v3;
        }
        __syncthreads();
    }

    #pragma unroll
    for (int i = 0; i < 4; i++) {
        float inv_l = 1.f / lrow[ty*4+i];
        #pragma unroll
        for (int j = 0; j < 4; j++)
            o[((size_t)(b * Sl + qt * 64 + ty * 4 + i) * Hn + h) * 64 + tx * 4 + j] =
                acc[i][j] * inv_l;
    }
}

// ---------------------------------------------------------------------------
// Chunked delta-rule memory scan. One block per batch, 256 threads.
// M [DV=64, DK=64] lives in shared across all 32 chunks.
// ---------------------------------------------------------------------------
__global__ void memscan_kernel(const float* __restrict__ z,
                               const float* __restrict__ M_init,
                               const float* __restrict__ w_eta, const float* __restrict__ b_eta,
                               const float* __restrict__ w_alpha, const float* __restrict__ b_alpha,
                               const float* __restrict__ w_gate, const float* __restrict__ b_gate,
                               float* __restrict__ mem_out) {
    __shared__ float Ms[64][64];    // M[v][d]
    __shared__ float chs[64][64];   // chunk[t][d]
    __shared__ float red2[16][64];  // column partial sums of `out`
    __shared__ float se[64], sa[64], sg[64], nrm[64];
    __shared__ float kmean[64], vt[64], diffv[64];
    __shared__ float red[256];
    __shared__ float sc_eta, sc_alpha, sc_gate, sc_scale;

    int b = blockIdx.x;
    int tid = threadIdx.x;
    int tx = tid & 15, ty = tid >> 4;

    #pragma unroll
    for (int i = 0; i < 16; i++) {
        int idx = tid + i * 256;
        Ms[idx >> 6][idx & 63] = M_init[idx];
    }
    __syncthreads();

    for (int c = 0; c < NCH; c++) {
        #pragma unroll
        for (int i = 0; i < 16; i++) {
            int idx = tid + i * 256;
            chs[idx >> 6][idx & 63] = z[((size_t)b * Sl + c * 64 + (idx >> 6)) * 64 + (idx & 63)];
        }
        __syncthreads();

        // out[t][v] = sum_d ch[t][d] * M[v][d]; write to global, keep col sums
        float o4[4][4] = {};
        #pragma unroll
        for (int d = 0; d < 64; d++) {
            float a0 = chs[ty*4+0][d], a1 = chs[ty*4+1][d];
            float a2 = chs[ty*4+2][d], a3 = chs[ty*4+3][d];
            float m0 = Ms[tx*4+0][d], m1 = Ms[tx*4+1][d];
            float m2 = Ms[tx*4+2][d], m3 = Ms[tx*4+3][d];
            o4[0][0] += a0*m0; o4[0][1] += a0*m1; o4[0][2] += a0*m2; o4[0][3] += a0*m3;
            o4[1][0] += a1*m0; o4[1][1] += a1*m1; o4[1][2] += a1*m2; o4[1][3] += a1*m3;
            o4[2][0] += a2*m0; o4[2][1] += a2*m1; o4[2][2] += a2*m2; o4[2][3] += a2*m3;
            o4[3][0] += a3*m0; o4[3][1] += a3*m1; o4[3][2] += a3*m2; o4[3][3] += a3*m3;
        }
        #pragma unroll
        for (int i = 0; i < 4; i++)
            #pragma unroll
            for (int j = 0; j < 4; j++)
                mem_out[((size_t)b * Sl + c * 64 + ty * 4 + i) * 64 + tx * 4 + j] = o4[i][j];
        #pragma unroll
        for (int j = 0; j < 4; j++)
            red2[ty][tx * 4 + j] = o4[0][j] + o4[1][j] + o4[2][j] + o4[3][j];
        __syncthreads();

        // per-token gates + norms
        if (tid < 64) {
            float de = 0.f, da = 0.f, dg = 0.f, nn = 0.f;
            #pragma unroll
            for (int d = 0; d < 64; d++) {
                float x = chs[tid][d];
                de += x * w_eta[d];
                da += x * w_alpha[d];
                dg += x * w_gate[d];
                nn += x * x;
            }
            se[tid] = 0.2f / (1.f + expf(-(de + b_eta[0])));
            sa[tid] = 0.5f + 0.5f / (1.f + expf(-(da + b_alpha[0])));
            sg[tid] = 1.f / (1.f + expf(-(dg + b_gate[0])));
            nrm[tid] = fmaxf(sqrtf(nn), 1e-6f);
        }
        __syncthreads();

        if (tid < 64) {
            float s = 0.f;
            #pragma unroll
            for (int t = 0; t < 64; t++) s += chs[t][tid] / nrm[t];
            kmean[tid] = s * (1.f / 64.f);
        } else if (tid < 128) {
            int vv = tid - 64;
            float s = 0.f;
            #pragma unroll
            for (int yy = 0; yy < 16; yy++) s += red2[yy][vv];
            vt[vv] = s * (1.f / 64.f);
        } else if (tid == 128) {
            float e = 0.f, a = 0.f, g = 0.f;
            #pragma unroll
            for (int t = 0; t < 64; t++) { e += se[t]; a += sa[t]; g += sg[t]; }
            sc_eta = e * (1.f / 64.f);
            sc_alpha = a * (1.f / 64.f);
            sc_gate = g * (1.f / 64.f);
        }
        __syncthreads();

        if (tid < 64) {
            float s = 0.f;
            #pragma unroll
            for (int d = 0; d < 64; d++) s += Ms[tid][d] * kmean[d];
            diffv[tid] = vt[tid] - s;
        }
        __syncthreads();

        // M update + Frobenius norm
        float eg = sc_eta * sc_gate, al = sc_alpha;
        float ss2 = 0.f;
        #pragma unroll
        for (int i = 0; i < 16; i++) {
            int idx = tid + i * 256;
            int vv = idx >> 6, d = idx & 63;
            float mn = al * Ms[vv][d] + eg * diffv[vv] * kmean[d];
            Ms[vv][d] = mn;
            ss2 += mn * mn;
        }
        red[tid] = ss2;
        __syncthreads();
        for (int st = 128; st > 0; st >>= 1) {
            if (tid < st) red[tid] += red[tid + st];
            __syncthreads();
        }
        if (tid == 0) {
            float fro = sqrtf(red[0]);
            sc_scale = fminf(1.f, 30.f / fmaxf(fro, 1e-6f));
        }
        __syncthreads();
        #pragma unroll
        for (int i = 0; i < 16; i++) {
            int idx = tid + i * 256;
            Ms[idx >> 6][idx & 63] *= sc_scale;
        }
        __syncthreads();
    }
}

// ---------------------------------------------------------------------------
extern "C" void kernel_launch(void* const* d_in, const int* in_sizes, int n_in,
                              void* d_out, int out_size) {
    const float* x       = (const float*)d_in[0];
    const float* Wq      = (const float*)d_in[1];
    const float* Wk      = (const float*)d_in[2];
    const float* Wv      = (const float*)d_in[3];
    const float* Wo      = (const float*)d_in[4];
    const float* Wmemin  = (const float*)d_in[5];
    const float* Wmemout = (const float*)d_in[6];
    const float* M_init  = (const float*)d_in[7];
    const float* w_eta   = (const float*)d_in[8];
    const float* b_eta   = (const float*)d_in[9];
    const float* w_alpha = (const float*)d_in[10];
    const float* b_alpha = (const float*)d_in[11];
    const float* w_gate  = (const float*)d_in[12];
    const float* b_gate  = (const float*)d_in[13];
    float* out = (float*)d_out;

    float *q, *k, *v, *attn, *z, *mem;
    cudaGetSymbolAddress((void**)&q, g_q);
    cudaGetSymbolAddress((void**)&k, g_k);
    cudaGetSymbolAddress((void**)&v, g_v);
    cudaGetSymbolAddress((void**)&attn, g_attn);
    cudaGetSymbolAddress((void**)&z, g_z);
    cudaGetSymbolAddress((void**)&mem, g_mem);

    // projections
    sgemm_kernel<<<dim3(Dm/64, MS/64), 256>>>(x, Wq, q, MS, Dm, Dm);           // q: 4096x1024
    sgemm_kernel<<<dim3((HKn*HDn)/64, MS/64), 256>>>(x, Wk, k, MS, HKn*HDn, Dm);
    sgemm_kernel<<<dim3((HKn*HDn)/64, MS/64), 256>>>(x, Wv, v, MS, HKn*HDn, Dm);
    sgemm_kernel<<<dim3(DKn/64, MS/64), 256>>>(x, Wmemin, z, MS, DKn, Dm);

    // rope
    rope_kernel<<<(Bsz*Sl*Hn*32 + 255)/256, 256>>>(q, Hn);
    rope_kernel<<<(Bsz*Sl*HKn*32 + 255)/256, 256>>>(k, HKn);

    // memory scan (independent of attention; cheap)
    memscan_kernel<<<Bsz, 256>>>(z, M_init, w_eta, b_eta, w_alpha, b_alpha,
                                 w_gate, b_gate, mem);

    // attention
    attn_kernel<<<dim3(Sl/64, Bsz*Hn), 256>>>(q, k, v, attn);

    // fused output: attn@Wo + mem@W_memout
    sgemm_dual_kernel<<<dim3(Dm/64, MS/64), 256>>>(attn, Wo, Dm,
                                                   mem, Wmemout, DVn,
                                                   out, Dm);
}

// round 2
// speedup vs baseline: 1.3682x; 1.3682x over previous
#include <cuda_runtime.h>
#include <math.h>
#include <stdint.h>

typedef unsigned long long ull;

// Problem constants
#define Bsz 2
#define Sl  2048
#define Dm  1024
#define Hn  16
#define HKn 4
#define HDn 64
#define DKn 64
#define DVn 64
#define NCH 32
#define MS  (Bsz*Sl)

// Scratch
__device__ float g_q[Bsz*Sl*Hn*HDn];
__device__ float g_k[Bsz*Sl*HKn*HDn];
__device__ float g_v[Bsz*Sl*HKn*HDn];
__device__ float g_attn[Bsz*Sl*Hn*HDn];
__device__ float g_z[Bsz*Sl*DKn];
__device__ float g_mem[Bsz*Sl*DVn];

// ---------------------------------------------------------------------------
// Packed-f32x2 SIMT GEMM. C[M,N] (+)= A1@B1 (+ A2@B2 if DUAL).
// BMxBN tile, TMxTN microtile, (BM/TM)*(BN/TN) threads.
// ---------------------------------------------------------------------------
template<int BM,int BN,int BK,int TM,int TN,bool DUAL>
__global__ __launch_bounds__((BM/TM)*(BN/TN))
void gemm_k(const float* __restrict__ A1, const float* __restrict__ B1, int K1,
            const float* __restrict__ A2, const float* __restrict__ B2, int K2,
            float* __restrict__ C, int N) {
    constexpr int THREADS = (BM/TM)*(BN/TN);
    __shared__ float As[BK][BM];
    __shared__ float Bs[BK][BN];
    int tid = threadIdx.x;
    int tx = tid % (BN/TN), ty = tid / (BN/TN);
    int row0 = blockIdx.y * BM, col0 = blockIdx.x * BN;
    ull acc[TM][TN/2] = {};
    #pragma unroll
    for (int ph = 0; ph < (DUAL ? 2 : 1); ph++) {
        const float* A = ph ? A2 : A1;
        const float* B = ph ? B2 : B1;
        int K = ph ? K2 : K1;
        for (int k0 = 0; k0 < K; k0 += BK) {
            constexpr int AV = BM*BK/(4*THREADS);
            #pragma unroll
            for (int vv = 0; vv < AV; vv++) {
                int vec = tid + vv*THREADS;
                int m = vec / (BK/4), kq = vec % (BK/4);
                float4 t = *(const float4*)&A[(size_t)(row0+m)*K + k0 + kq*4];
                As[kq*4+0][m] = t.x; As[kq*4+1][m] = t.y;
                As[kq*4+2][m] = t.z; As[kq*4+3][m] = t.w;
            }
            constexpr int BV = BN*BK/(4*THREADS);
            #pragma unroll
            for (int vv = 0; vv < BV; vv++) {
                int vec = tid + vv*THREADS;
                int kk = vec / (BN/4), nq = vec % (BN/4);
                *(float4*)&Bs[kk][nq*4] = *(const float4*)&B[(size_t)(k0+kk)*N + col0 + nq*4];
            }
            __syncthreads();
            #pragma unroll
            for (int k = 0; k < BK; k++) {
                float a[TM];
                #pragma unroll
                for (int i = 0; i < TM; i += 4)
                    *(float4*)&a[i] = *(const float4*)&As[k][ty*TM + i];
                ull bp[TN/2];
                #pragma unroll
                for (int j = 0; j < TN/2; j++)
                    bp[j] = *(const ull*)&Bs[k][tx*TN + 2*j];
                #pragma unroll
                for (int i = 0; i < TM; i++) {
                    ull ad; asm("mov.b64 %0, {%1, %1};" : "=l"(ad) : "f"(a[i]));
                    #pragma unroll
                    for (int j = 0; j < TN/2; j++)
                        asm("fma.rn.f32x2 %0, %1, %2, %0;"
                            : "+l"(acc[i][j]) : "l"(ad), "l"(bp[j]));
                }
            }
            __syncthreads();
        }
    }
    #pragma unroll
    for (int i = 0; i < TM; i++) {
        float out[TN];
        #pragma unroll
        for (int j = 0; j < TN/2; j++) {
            float2 p = *(float2*)&acc[i][j];
            out[2*j] = p.x; out[2*j+1] = p.y;
        }
        #pragma unroll
        for (int j = 0; j < TN; j += 4)
            *(float4*)&C[(size_t)(row0+ty*TM+i)*N + col0 + tx*TN + j] = *(float4*)&out[j];
    }
}

// ---------------------------------------------------------------------------
// RoPE in place on [B, S, nheads, 64].
// ---------------------------------------------------------------------------
__global__ void rope_kernel(float* __restrict__ t, int nheads) {
    int idx = blockIdx.x * blockDim.x + threadIdx.x;
    int total = Bsz * Sl * nheads * 32;
    if (idx >= total) return;
    int j = idx & 31;
    int h = (idx >> 5) % nheads;
    int s = ((idx >> 5) / nheads) % Sl;
    int b = idx / (32 * nheads * Sl);
    float inv = powf(500000.0f, -(float)(2 * j) / 64.0f);
    float ang = (float)s * inv;
    float c, sn;
    __sincosf(ang, &sn, &c);
    size_t base = ((size_t)(b * Sl + s) * nheads + h) * 64;
    float u1 = t[base + j], u2 = t[base + j + 32];
    t[base + j]      = u1 * c - u2 * sn;
    t[base + j + 32] = u2 * c + u1 * sn;
}

// ---------------------------------------------------------------------------
// Flash attention: q-tile 128, kv-tile 64, 128 threads, 8x8 packed microtile.
// Dynamic smem, transposed layouts so inner loops are LDS.128/LDS.64.
// ---------------------------------------------------------------------------
#define QS_STRIDE 132
#define KS_STRIDE 68
#define ATTN_SMEM_FLOATS (64*QS_STRIDE + 64*KS_STRIDE + 64*KS_STRIDE + 64*QS_STRIDE + 3*128)
#define ATTN_SMEM_BYTES (ATTN_SMEM_FLOATS * 4)

__global__ __launch_bounds__(128)
void attn_kernel(const float* __restrict__ q, const float* __restrict__ k,
                 const float* __restrict__ v, float* __restrict__ o) {
    extern __shared__ float sm[];
    float* qs = sm;                         // [d=64][r=128] stride 132
    float* ks = qs + 64*QS_STRIDE;          // [d=64][c=64]  stride 68
    float* vs = ks + 64*KS_STRIDE;          // [c=64][d=64]  stride 68
    float* ss = vs + 64*KS_STRIDE;          // [c=64][r=128] stride 132
    float* mrow = ss + 64*QS_STRIDE;        // [128]
    float* lrow = mrow + 128;
    float* frow = lrow + 128;

    int qt = blockIdx.x;                    // 0..15 (128 q rows each)
    int bh = blockIdx.y;
    int b = bh >> 4, h = bh & 15, kh = h >> 2;
    int tid = threadIdx.x;
    int tx = tid & 7, ty = tid >> 3;        // 8 col-groups x 16 row-groups
    const float scale = 0.125f;

    // Load Q tile (128 rows x 64 d), transpose into qs[d][r]
    #pragma unroll 4
    for (int i = 0; i < 64; i++) {
        int idx = tid + i * 128;
        int r = idx >> 6, d = idx & 63;
        qs[d*QS_STRIDE + r] = q[((size_t)(b*Sl + qt*128 + r)*Hn + h)*64 + d] * scale;
    }
    mrow[tid] = -3e38f;
    lrow[tid] = 0.f;
    ull accO[8][4] = {};
    __syncthreads();

    int ktmax = 2*qt + 1;
    for (int kt = 0; kt <= ktmax; kt++) {
        // Load K (transposed) and V tiles: 64 rows x 64 d
        #pragma unroll 4
        for (int i = 0; i < 32; i++) {
            int idx = tid + i * 128;
            int c = idx >> 6, d = idx & 63;
            size_t g = ((size_t)(b*Sl + kt*64 + c)*HKn + kh)*64 + d;
            ks[d*KS_STRIDE + c] = k[g];
            vs[c*KS_STRIDE + d] = v[g];
        }
        __syncthreads();

        // QK^T: 128x64 scores
        ull accS[8][4] = {};
        #pragma unroll 2
        for (int d = 0; d < 64; d++) {
            float a[8];
            *(float4*)&a[0] = *(const float4*)&qs[d*QS_STRIDE + ty*8];
            *(float4*)&a[4] = *(const float4*)&qs[d*QS_STRIDE + ty*8 + 4];
            ull bp[4];
            #pragma unroll
            for (int j = 0; j < 4; j++)
                bp[j] = *(const ull*)&ks[d*KS_STRIDE + tx*8 + 2*j];
            #pragma unroll
            for (int i = 0; i < 8; i++) {
                ull ad; asm("mov.b64 %0, {%1, %1};" : "=l"(ad) : "f"(a[i]));
                #pragma unroll
                for (int j = 0; j < 4; j++)
                    asm("fma.rn.f32x2 %0, %1, %2, %0;"
                        : "+l"(accS[i][j]) : "l"(ad), "l"(bp[j]));
            }
        }

        // Mask (diagonal tiles) + write transposed into ss[c][r]
        bool diag = (kt >= 2*qt);
        #pragma unroll
        for (int i = 0; i < 8; i++) {
            int r = ty*8 + i, rg = qt*128 + r;
            #pragma unroll
            for (int j = 0; j < 4; j++) {
                float2 p = *(float2*)&accS[i][j];
                int c0 = tx*8 + 2*j, cg = kt*64 + c0;
                if (diag) {
                    if (cg > rg)     p.x = -3e38f;
                    if (cg + 1 > rg) p.y = -3e38f;
                }
                ss[(c0)  *QS_STRIDE + r] = p.x;
                ss[(c0+1)*QS_STRIDE + r] = p.y;
            }
        }
        __syncthreads();

        // Online softmax: one thread per row (128 threads = 128 rows)
        {
            float m_old = mrow[tid];
            float mx = m_old;
            #pragma unroll
            for (int c = 0; c < 64; c++) mx = fmaxf(mx, ss[c*QS_STRIDE + tid]);
            float sum = 0.f;
            #pragma unroll
            for (int c = 0; c < 64; c++) {
                float p = __expf(ss[c*QS_STRIDE + tid] - mx);
                ss[c*QS_STRIDE + tid] = p;
                sum += p;
            }
            float f = __expf(m_old - mx);
            frow[tid] = f;
            lrow[tid] = lrow[tid]*f + sum;
            mrow[tid] = mx;
        }
        __syncthreads();

        // Rescale accumulators
        #pragma unroll
        for (int i = 0; i < 8; i++) {
            float f = frow[ty*8 + i];
            ull fd; asm("mov.b64 %0, {%1, %1};" : "=l"(fd) : "f"(f));
            #pragma unroll
            for (int j = 0; j < 4; j++)
                asm("mul.rn.f32x2 %0, %0, %1;" : "+l"(accO[i][j]) : "l"(fd));
        }

        // P @ V accumulate
        #pragma unroll 2
        for (int c = 0; c < 64; c++) {
            float a[8];
            *(float4*)&a[0] = *(const float4*)&ss[c*QS_STRIDE + ty*8];
            *(float4*)&a[4] = *(const float4*)&ss[c*QS_STRIDE + ty*8 + 4];
            ull bp[4];
            #pragma unroll
            for (int j = 0; j < 4; j++)
                bp[j] = *(const ull*)&vs[c*KS_STRIDE + tx*8 + 2*j];
            #pragma unroll
            for (int i = 0; i < 8; i++) {
                ull ad; asm("mov.b64 %0, {%1, %1};" : "=l"(ad) : "f"(a[i]));
                #pragma unroll
                for (int j = 0; j < 4; j++)
                    asm("fma.rn.f32x2 %0, %1, %2, %0;"
                        : "+l"(accO[i][j]) : "l"(ad), "l"(bp[j]));
            }
        }
        __syncthreads();
    }

    // Epilogue
    #pragma unroll
    for (int i = 0; i < 8; i++) {
        int r = ty*8 + i;
        float inv_l = 1.f / lrow[r];
        float out8[8];
        #pragma unroll
        for (int j = 0; j < 4; j++) {
            float2 p = *(float2*)&accO[i][j];
            out8[2*j]   = p.x * inv_l;
            out8[2*j+1] = p.y * inv_l;
        }
        size_t base = ((size_t)(b*Sl + qt*128 + r)*Hn + h)*64 + tx*8;
        *(float4*)&o[base]   = *(float4*)&out8[0];
        *(float4*)&o[base+4] = *(float4*)&out8[4];
    }
}

// ---------------------------------------------------------------------------
// Chunked delta-rule memory scan (unchanged; runs on side stream).
// ---------------------------------------------------------------------------
__global__ void memscan_kernel(const float* __restrict__ z,
                               const float* __restrict__ M_init,
                               const float* __restrict__ w_eta, const float* __restrict__ b_eta,
                               const float* __restrict__ w_alpha, const float* __restrict__ b_alpha,
                               const float* __restrict__ w_gate, const float* __restrict__ b_gate,
                               float* __restrict__ mem_out) {
    __shared__ float Ms[64][64];
    __shared__ float chs[64][64];
    __shared__ float red2[16][64];
    __shared__ float se[64], sa[64], sg[64], nrm[64];
    __shared__ float kmean[64], vt[64], diffv[64];
    __shared__ float red[256];
    __shared__ float sc_eta, sc_alpha, sc_gate, sc_scale;

    int b = blockIdx.x;
    int tid = threadIdx.x;
    int tx = tid & 15, ty = tid >> 4;

    #pragma unroll
    for (int i = 0; i < 16; i++) {
        int idx = tid + i * 256;
        Ms[idx >> 6][idx & 63] = M_init[idx];
    }
    __syncthreads();

    for (int c = 0; c < NCH; c++) {
        #pragma unroll
        for (int i = 0; i < 16; i++) {
            int idx = tid + i * 256;
            chs[idx >> 6][idx & 63] = z[((size_t)b * Sl + c * 64 + (idx >> 6)) * 64 + (idx & 63)];
        }
        __syncthreads();

        float o4[4][4] = {};
        #pragma unroll
        for (int d = 0; d < 64; d++) {
            float a0 = chs[ty*4+0][d], a1 = chs[ty*4+1][d];
            float a2 = chs[ty*4+2][d], a3 = chs[ty*4+3][d];
            float m0 = Ms[tx*4+0][d], m1 = Ms[tx*4+1][d];
            float m2 = Ms[tx*4+2][d], m3 = Ms[tx*4+3][d];
            o4[0][0] += a0*m0; o4[0][1] += a0*m1; o4[0][2] += a0*m2; o4[0][3] += a0*m3;
            o4[1][0] += a1*m0; o4[1][1] += a1*m1; o4[1][2] += a1*m2; o4[1][3] += a1*m3;
            o4[2][0] += a2*m0; o4[2][1] += a2*m1; o4[2][2] += a2*m2; o4[2][3] += a2*m3;
            o4[3][0] += a3*m0; o4[3][1] += a3*m1; o4[3][2] += a3*m2; o4[3][3] += a3*m3;
        }
        #pragma unroll
        for (int i = 0; i < 4; i++)
            #pragma unroll
            for (int j = 0; j < 4; j++)
                mem_out[((size_t)b * Sl + c * 64 + ty * 4 + i) * 64 + tx * 4 + j] = o4[i][j];
        #pragma unroll
        for (int j = 0; j < 4; j++)
            red2[ty][tx * 4 + j] = o4[0][j] + o4[1][j] + o4[2][j] + o4[3][j];
        __syncthreads();

        if (tid < 64) {
            float de = 0.f, da = 0.f, dg = 0.f, nn = 0.f;
            #pragma unroll
            for (int d = 0; d < 64; d++) {
                float x = chs[tid][d];
                de += x * w_eta[d];
                da += x * w_alpha[d];
                dg += x * w_gate[d];
                nn += x * x;
            }
            se[tid] = 0.2f / (1.f + expf(-(de + b_eta[0])));
            sa[tid] = 0.5f + 0.5f / (1.f + expf(-(da + b_alpha[0])));
            sg[tid] = 1.f / (1.f + expf(-(dg + b_gate[0])));
            nrm[tid] = fmaxf(sqrtf(nn), 1e-6f);
        }
        __syncthreads();

        if (tid < 64) {
            float s = 0.f;
            #pragma unroll
            for (int t = 0; t < 64; t++) s += chs[t][tid] / nrm[t];
            kmean[tid] = s * (1.f / 64.f);
        } else if (tid < 128) {
            int vv = tid - 64;
            float s = 0.f;
            #pragma unroll
            for (int yy = 0; yy < 16; yy++) s += red2[yy][vv];
            vt[vv] = s * (1.f / 64.f);
        } else if (tid == 128) {
            float e = 0.f, a = 0.f, g = 0.f;
            #pragma unroll
            for (int t = 0; t < 64; t++) { e += se[t]; a += sa[t]; g += sg[t]; }
            sc_eta = e * (1.f / 64.f);
            sc_alpha = a * (1.f / 64.f);
            sc_gate = g * (1.f / 64.f);
        }
        __syncthreads();

        if (tid < 64) {
            float s = 0.f;
            #pragma unroll
            for (int d = 0; d < 64; d++) s += Ms[tid][d] * kmean[d];
            diffv[tid] = vt[tid] - s;
        }
        __syncthreads();

        float eg = sc_eta * sc_gate, al = sc_alpha;
        float ss2 = 0.f;
        #pragma unroll
        for (int i = 0; i < 16; i++) {
            int idx = tid + i * 256;
            int vv = idx >> 6, d = idx & 63;
            float mn = al * Ms[vv][d] + eg * diffv[vv] * kmean[d];
            Ms[vv][d] = mn;
            ss2 += mn * mn;
        }
        red[tid] = ss2;
        __syncthreads();
        for (int st = 128; st > 0; st >>= 1) {
            if (tid < st) red[tid] += red[tid + st];
            __syncthreads();
        }
        if (tid == 0) {
            float fro = sqrtf(red[0]);
            sc_scale = fminf(1.f, 30.f / fmaxf(fro, 1e-6f));
        }
        __syncthreads();
        #pragma unroll
        for (int i = 0; i < 16; i++) {
            int idx = tid + i * 256;
            Ms[idx >> 6][idx & 63] *= sc_scale;
        }
        __syncthreads();
    }
}

// ---------------------------------------------------------------------------
extern "C" void kernel_launch(void* const* d_in, const int* in_sizes, int n_in,
                              void* d_out, int out_size) {
    const float* x       = (const float*)d_in[0];
    const float* Wq      = (const float*)d_in[1];
    const float* Wk      = (const float*)d_in[2];
    const float* Wv      = (const float*)d_in[3];
    const float* Wo      = (const float*)d_in[4];
    const float* Wmemin  = (const float*)d_in[5];
    const float* Wmemout = (const float*)d_in[6];
    const float* M_init  = (const float*)d_in[7];
    const float* w_eta   = (const float*)d_in[8];
    const float* b_eta   = (const float*)d_in[9];
    const float* w_alpha = (const float*)d_in[10];
    const float* b_alpha = (const float*)d_in[11];
    const float* w_gate  = (const float*)d_in[12];
    const float* b_gate  = (const float*)d_in[13];
    float* out = (float*)d_out;

    float *q, *k, *v, *attn, *z, *mem;
    cudaGetSymbolAddress((void**)&q, g_q);
    cudaGetSymbolAddress((void**)&k, g_k);
    cudaGetSymbolAddress((void**)&v, g_v);
    cudaGetSymbolAddress((void**)&attn, g_attn);
    cudaGetSymbolAddress((void**)&z, g_z);
    cudaGetSymbolAddress((void**)&mem, g_mem);

    static cudaStream_t s2 = nullptr;
    static cudaEvent_t evZ = nullptr, evM = nullptr;
    static int inited = 0;
    if (!inited) {
        cudaStreamCreateWithFlags(&s2, cudaStreamNonBlocking);
        cudaEventCreateWithFlags(&evZ, cudaEventDisableTiming);
        cudaEventCreateWithFlags(&evM, cudaEventDisableTiming);
        cudaFuncSetAttribute(attn_kernel,
                             cudaFuncAttributeMaxDynamicSharedMemorySize, ATTN_SMEM_BYTES);
        inited = 1;
    }

    // z projection first, then fork the serial memscan onto a side stream
    gemm_k<128,64,16,8,4,false><<<dim3(1, MS/128), 256>>>(x, Wmemin, Dm,
                                                          nullptr, nullptr, 0, z, DKn);
    cudaEventRecord(evZ, 0);
    cudaStreamWaitEvent(s2, evZ, 0);
    memscan_kernel<<<Bsz, 256, 0, s2>>>(z, M_init, w_eta, b_eta, w_alpha, b_alpha,
                                        w_gate, b_gate, mem);
    cudaEventRecord(evM, s2);

    // projections
    gemm_k<128,128,8,8,8,false><<<dim3(Dm/128, MS/128), 256>>>(x, Wq, Dm,
                                                               nullptr, nullptr, 0, q, Dm);
    gemm_k<128,128,8,8,8,false><<<dim3((HKn*HDn)/128, MS/128), 256>>>(x, Wk, Dm,
                                                               nullptr, nullptr, 0, k, HKn*HDn);
    gemm_k<128,128,8,8,8,false><<<dim3((HKn*HDn)/128, MS/128), 256>>>(x, Wv, Dm,
                                                               nullptr, nullptr, 0, v, HKn*HDn);

    // rope
    rope_kernel<<<(Bsz*Sl*Hn*32 + 255)/256, 256>>>(q, Hn);
    rope_kernel<<<(Bsz*Sl*HKn*32 + 255)/256, 256>>>(k, HKn);

    // attention
    attn_kernel<<<dim3(Sl/128, Bsz*Hn), 128, ATTN_SMEM_BYTES>>>(q, k, v, attn);

    // join memscan, then fused output GEMM
    cudaStreamWaitEvent((cudaStream_t)0, evM, 0);
    gemm_k<128,128,8,8,8,true><<<dim3(Dm/128, MS/128), 256>>>(attn, Wo, Hn*HDn,
                                                              mem, Wmemout, DVn,
                                                              out, Dm);
}

// round 3
// speedup vs baseline: 1.5447x; 1.1290x over previous
#include <cuda_runtime.h>
#include <math.h>
#include <stdint.h>

typedef unsigned long long ull;

#define Bsz 2
#define Sl  2048
#define Dm  1024
#define Hn  16
#define HKn 4
#define HDn 64
#define DKn 64
#define DVn 64
#define NCH 32
#define MS  (Bsz*Sl)

__device__ float g_q[Bsz*Sl*Hn*HDn];
__device__ float g_k[Bsz*Sl*HKn*HDn];
__device__ float g_v[Bsz*Sl*HKn*HDn];
__device__ float g_attn[Bsz*Sl*Hn*HDn];
__device__ float g_z[Bsz*Sl*DKn];
__device__ float g_mem[Bsz*Sl*DVn];

__device__ __forceinline__ unsigned su32(const void* p) {
    unsigned a;
    asm("{.reg .u64 t; cvta.to.shared.u64 t, %1; cvt.u32.u64 %0, t;}" : "=r"(a) : "l"(p));
    return a;
}
#define CP16(dst, src) asm volatile("cp.async.ca.shared.global [%0], [%1], 16;" :: "r"(dst), "l"(src))
#define CPCOMMIT()     asm volatile("cp.async.commit_group;")
#define CPWAIT1()      asm volatile("cp.async.wait_group 1;")

// ===========================================================================
// GEMM building blocks: BM=128, BN=64, BK=16, 128 threads, 8x8 microtile,
// packed f32x2 FMA, register double-buffering of global loads.
// As stride 132 (padded), Bs stride 64.
// ===========================================================================
__device__ __forceinline__ void gemm_load_regs(const float* __restrict__ A,
                                               const float* __restrict__ B,
                                               int K, int N, int row0, int col0, int k0,
                                               int tid, float4 ar[4], float4 br[2]) {
    #pragma unroll
    for (int i = 0; i < 4; i++) {
        int vec = tid + i * 128;
        int m = vec >> 2, kq = vec & 3;
        ar[i] = *(const float4*)&A[(size_t)(row0 + m) * K + k0 + kq * 4];
    }
    #pragma unroll
    for (int i = 0; i < 2; i++) {
        int vec = tid + i * 128;
        int kk = vec >> 4, nq = vec & 15;
        br[i] = *(const float4*)&B[(size_t)(k0 + kk) * N + col0 + nq * 4];
    }
}

__device__ __forceinline__ void gemm_sts(float* As, float* Bs, int tid,
                                         const float4 ar[4], const float4 br[2]) {
    #pragma unroll
    for (int i = 0; i < 4; i++) {
        int vec = tid + i * 128;
        int m = vec >> 2, kq = vec & 3;
        As[(kq * 4 + 0) * 132 + m] = ar[i].x;
        As[(kq * 4 + 1) * 132 + m] = ar[i].y;
        As[(kq * 4 + 2) * 132 + m] = ar[i].z;
        As[(kq * 4 + 3) * 132 + m] = ar[i].w;
    }
    #pragma unroll
    for (int i = 0; i < 2; i++) {
        int vec = tid + i * 128;
        int kk = vec >> 4, nq = vec & 15;
        *(float4*)&Bs[kk * 64 + nq * 4] = br[i];
    }
}

__device__ __forceinline__ void gemm_compute(const float* As, const float* Bs,
                                             int ty, int tx, ull acc[8][4]) {
    #pragma unroll
    for (int kk = 0; kk < 16; kk++) {
        float a[8];
        *(float4*)&a[0] = *(const float4*)&As[kk * 132 + ty * 8];
        *(float4*)&a[4] = *(const float4*)&As[kk * 132 + ty * 8 + 4];
        ull bp[4];
        #pragma unroll
        for (int j = 0; j < 4; j++) bp[j] = *(const ull*)&Bs[kk * 64 + tx * 8 + 2 * j];
        #pragma unroll
        for (int i = 0; i < 8; i++) {
            ull ad; asm("mov.b64 %0, {%1, %1};" : "=l"(ad) : "f"(a[i]));
            #pragma unroll
            for (int j = 0; j < 4; j++)
                asm("fma.rn.f32x2 %0, %1, %2, %0;" : "+l"(acc[i][j]) : "l"(ad), "l"(bp[j]));
        }
    }
}

__device__ __forceinline__ void gemm_epilogue(ull acc[8][4], float* __restrict__ C,
                                              int N, int row0, int col0, int ty, int tx) {
    #pragma unroll
    for (int i = 0; i < 8; i++) {
        float o8[8];
        #pragma unroll
        for (int j = 0; j < 4; j++) {
            float2 p = *(float2*)&acc[i][j];
            o8[2 * j] = p.x; o8[2 * j + 1] = p.y;
        }
        size_t base = (size_t)(row0 + ty * 8 + i) * N + col0 + tx * 8;
        *(float4*)&C[base]     = *(float4*)&o8[0];
        *(float4*)&C[base + 4] = *(float4*)&o8[4];
    }
}

// ---------------------------------------------------------------------------
// Fused projection GEMM: x @ {Wq|Wk|Wv|Wmemin} selected per column tile.
// grid = (25, 32), block = 128.
// ---------------------------------------------------------------------------
__global__ __launch_bounds__(128)
void proj_kernel(const float* __restrict__ x,
                 const float* __restrict__ Wq, const float* __restrict__ Wk,
                 const float* __restrict__ Wv, const float* __restrict__ Wz,
                 float* __restrict__ q, float* __restrict__ kout,
                 float* __restrict__ vout, float* __restrict__ z) {
    __shared__ float As[16 * 132];
    __shared__ float Bs[16 * 64];
    int tid = threadIdx.x;
    int tx = tid & 7, ty = tid >> 3;
    int ct = blockIdx.x;
    int row0 = blockIdx.y * 128;
    const float* B; float* C; int N, col0;
    if (ct < 16)      { B = Wq; C = q;    N = 1024; col0 = ct * 64; }
    else if (ct < 20) { B = Wk; C = kout; N = 256;  col0 = (ct - 16) * 64; }
    else if (ct < 24) { B = Wv; C = vout; N = 256;  col0 = (ct - 20) * 64; }
    else              { B = Wz; C = z;    N = 64;   col0 = 0; }

    ull acc[8][4] = {};
    float4 ar[4]; float4 br[2];
    gemm_load_regs(x, B, 1024, N, row0, col0, 0, tid, ar, br);
    for (int k0 = 0; k0 < 1024; k0 += 16) {
        gemm_sts(As, Bs, tid, ar, br);
        __syncthreads();
        if (k0 + 16 < 1024)
            gemm_load_regs(x, B, 1024, N, row0, col0, k0 + 16, tid, ar, br);
        gemm_compute(As, Bs, ty, tx, acc);
        __syncthreads();
    }
    gemm_epilogue(acc, C, N, row0, col0, ty, tx);
}

// ---------------------------------------------------------------------------
// Dual GEMM: C = A1@B1 + A2@B2. grid = (16, 32), block = 128.
// ---------------------------------------------------------------------------
__global__ __launch_bounds__(128)
void dual_gemm_kernel(const float* __restrict__ A1, const float* __restrict__ B1, int K1,
                      const float* __restrict__ A2, const float* __restrict__ B2, int K2,
                      float* __restrict__ C, int N) {
    __shared__ float As[16 * 132];
    __shared__ float Bs[16 * 64];
    int tid = threadIdx.x;
    int tx = tid & 7, ty = tid >> 3;
    int row0 = blockIdx.y * 128, col0 = blockIdx.x * 64;
    ull acc[8][4] = {};
    float4 ar[4]; float4 br[2];
    #pragma unroll
    for (int ph = 0; ph < 2; ph++) {
        const float* A = ph ? A2 : A1;
        const float* B = ph ? B2 : B1;
        int K = ph ? K2 : K1;
        gemm_load_regs(A, B, K, N, row0, col0, 0, tid, ar, br);
        for (int k0 = 0; k0 < K; k0 += 16) {
            gemm_sts(As, Bs, tid, ar, br);
            __syncthreads();
            if (k0 + 16 < K)
                gemm_load_regs(A, B, K, N, row0, col0, k0 + 16, tid, ar, br);
            gemm_compute(As, Bs, ty, tx, acc);
            __syncthreads();
        }
    }
    gemm_epilogue(acc, C, N, row0, col0, ty, tx);
}

// ---------------------------------------------------------------------------
// RoPE in place on [B, S, nheads, 64].
// ---------------------------------------------------------------------------
__global__ void rope_kernel(float* __restrict__ t, int nheads) {
    int idx = blockIdx.x * blockDim.x + threadIdx.x;
    int total = Bsz * Sl * nheads * 32;
    if (idx >= total) return;
    int j = idx & 31;
    int h = (idx >> 5) % nheads;
    int s = ((idx >> 5) / nheads) % Sl;
    int b = idx / (32 * nheads * Sl);
    float inv = powf(500000.0f, -(float)(2 * j) / 64.0f);
    float ang = (float)s * inv;
    float c, sn;
    __sincosf(ang, &sn, &c);
    size_t base = ((size_t)(b * Sl + s) * nheads + h) * 64;
    float u1 = t[base + j], u2 = t[base + j + 32];
    t[base + j]      = u1 * c - u2 * sn;
    t[base + j + 32] = u2 * c + u1 * sn;
}

// ---------------------------------------------------------------------------
// Flash attention: 128q x 64kv tiles, 256 threads, register softmax via shfl,
// cp.async double-buffered V, register-prefetched K, swizzled P store.
// ---------------------------------------------------------------------------
#define QSS 132
#define KSS 66
#define ATTN_FLOATS (64*QSS + 64*KSS + 2*64*64 + 64*128)
#define ATTN_BYTES (ATTN_FLOATS * 4)

__global__ __launch_bounds__(256)
void attn_kernel(const float* __restrict__ q, const float* __restrict__ k,
                 const float* __restrict__ v, float* __restrict__ o) {
    extern __shared__ float sm[];
    float* qs = sm;                    // [d][r] stride 132
    float* ks = qs + 64 * QSS;         // [d][c] stride 66
    float* vs = ks + 64 * KSS;         // 2 x [c][d] stride 64
    float* ss = vs + 2 * 64 * 64;      // [c][r swizzled] stride 128

    int qt = blockIdx.x;
    int bh = blockIdx.y;
    int b = bh >> 4, h = bh & 15, kh = h >> 2;
    int tid = threadIdx.x;
    int tx = tid & 7, ty = tid >> 3;   // tx 0..7 colgroups, ty 0..31 rowgroups

    // Load Q tile transposed + scaled
    size_t qbase = ((size_t)(b * Sl + qt * 128) * Hn + h) * 64;
    #pragma unroll
    for (int i = 0; i < 8; i++) {
        int vec = tid + i * 256;
        int r = vec >> 4, dq = vec & 15;
        float4 t = *(const float4*)&q[qbase + (size_t)r * Hn * 64 + dq * 4];
        qs[(dq * 4 + 0) * QSS + r] = t.x * 0.125f;
        qs[(dq * 4 + 1) * QSS + r] = t.y * 0.125f;
        qs[(dq * 4 + 2) * QSS + r] = t.z * 0.125f;
        qs[(dq * 4 + 3) * QSS + r] = t.w * 0.125f;
    }

    size_t kvbase = ((size_t)(b * Sl) * HKn + kh) * 64;
    int ktmax = 2 * qt + 1;

    // Prefetch V(0) via cp.async into buffer 0
    {
        unsigned dst = su32(vs);
        #pragma unroll
        for (int i = 0; i < 4; i++) {
            int vec = tid + i * 256;
            int c = vec >> 4, dq = vec & 15;
            CP16(dst + (unsigned)((c * 64 + dq * 4) * 4),
                 &v[kvbase + (size_t)c * HKn * 64 + dq * 4]);
        }
        CPCOMMIT();
    }
    // Prefetch K(0) into registers
    float4 kr[4];
    #pragma unroll
    for (int i = 0; i < 4; i++) {
        int vec = tid + i * 256;
        int c = vec >> 4, dq = vec & 15;
        kr[i] = *(const float4*)&k[kvbase + (size_t)c * HKn * 64 + dq * 4];
    }

    float m_reg[4], l_reg[4];
    ull accO[4][4] = {};
    #pragma unroll
    for (int i = 0; i < 4; i++) { m_reg[i] = -3e38f; l_reg[i] = 0.f; }

    __syncthreads();   // qs visible

    for (int kt = 0; kt <= ktmax; kt++) {
        // Store prefetched K (transposed) to smem
        #pragma unroll
        for (int i = 0; i < 4; i++) {
            int vec = tid + i * 256;
            int c = vec >> 4, dq = vec & 15;
            ks[(dq * 4 + 0) * KSS + c] = kr[i].x;
            ks[(dq * 4 + 1) * KSS + c] = kr[i].y;
            ks[(dq * 4 + 2) * KSS + c] = kr[i].z;
            ks[(dq * 4 + 3) * KSS + c] = kr[i].w;
        }
        // Issue V(kt+1) cp.async into the other buffer
        if (kt < ktmax) {
            unsigned dst = su32(vs + ((kt + 1) & 1) * 4096);
            size_t base = kvbase + (size_t)(kt + 1) * 64 * HKn * 64;
            #pragma unroll
            for (int i = 0; i < 4; i++) {
                int vec = tid + i * 256;
                int c = vec >> 4, dq = vec & 15;
                CP16(dst + (unsigned)((c * 64 + dq * 4) * 4),
                     &v[base + (size_t)c * HKn * 64 + dq * 4]);
            }
        }
        CPCOMMIT();
        __syncthreads();   // ks visible; prev iteration's reads done

        // Prefetch K(kt+1) into registers
        if (kt < ktmax) {
            size_t base = kvbase + (size_t)(kt + 1) * 64 * HKn * 64;
            #pragma unroll
            for (int i = 0; i < 4; i++) {
                int vec = tid + i * 256;
                int c = vec >> 4, dq = vec & 15;
                kr[i] = *(const float4*)&k[base + (size_t)c * HKn * 64 + dq * 4];
            }
        }

        // Scores: rows ty*4+i, cols tx*8+j
        ull accS[4][4] = {};
        #pragma unroll 2
        for (int d = 0; d < 64; d++) {
            float4 a4 = *(const float4*)&qs[d * QSS + ty * 4];
            float a[4] = {a4.x, a4.y, a4.z, a4.w};
            ull bp[4];
            #pragma unroll
            for (int j = 0; j < 4; j++) bp[j] = *(const ull*)&ks[d * KSS + tx * 8 + 2 * j];
            #pragma unroll
            for (int i = 0; i < 4; i++) {
                ull ad; asm("mov.b64 %0, {%1, %1};" : "=l"(ad) : "f"(a[i]));
                #pragma unroll
                for (int j = 0; j < 4; j++)
                    asm("fma.rn.f32x2 %0, %1, %2, %0;" : "+l"(accS[i][j]) : "l"(ad), "l"(bp[j]));
            }
        }

        // Unpack + causal mask
        float s[4][8];
        bool diag = (kt >= 2 * qt);
        #pragma unroll
        for (int i = 0; i < 4; i++) {
            #pragma unroll
            for (int j = 0; j < 4; j++) {
                float2 p = *(float2*)&accS[i][j];
                s[i][2 * j] = p.x; s[i][2 * j + 1] = p.y;
            }
            if (diag) {
                int rg = qt * 128 + ty * 4 + i;
                #pragma unroll
                for (int j = 0; j < 8; j++) {
                    int cg = kt * 64 + tx * 8 + j;
                    if (cg > rg) s[i][j] = -3e38f;
                }
            }
        }

        // Register online softmax (8-lane shfl groups share a row)
        float frow[4];
        #pragma unroll
        for (int i = 0; i < 4; i++) {
            float mx = m_reg[i];
            #pragma unroll
            for (int j = 0; j < 8; j++) mx = fmaxf(mx, s[i][j]);
            mx = fmaxf(mx, __shfl_xor_sync(0xffffffffu, mx, 1));
            mx = fmaxf(mx, __shfl_xor_sync(0xffffffffu, mx, 2));
            mx = fmaxf(mx, __shfl_xor_sync(0xffffffffu, mx, 4));
            float f = __expf(m_reg[i] - mx);
            m_reg[i] = mx;
            float sum = 0.f;
            #pragma unroll
            for (int j = 0; j < 8; j++) {
                float p = __expf(s[i][j] - mx);
                s[i][j] = p;
                sum += p;
            }
            sum += __shfl_xor_sync(0xffffffffu, sum, 1);
            sum += __shfl_xor_sync(0xffffffffu, sum, 2);
            sum += __shfl_xor_sync(0xffffffffu, sum, 4);
            l_reg[i] = l_reg[i] * f + sum;
            frow[i] = f;
        }
        // Rescale accO
        #pragma unroll
        for (int i = 0; i < 4; i++) {
            ull fd; asm("mov.b64 %0, {%1, %1};" : "=l"(fd) : "f"(frow[i]));
            #pragma unroll
            for (int j = 0; j < 4; j++)
                asm("mul.rn.f32x2 %0, %0, %1;" : "+l"(accO[i][j]) : "l"(fd));
        }
        // Store P transposed with XOR swizzle: ss[c][4*(ty^tx)..]
        #pragma unroll
        for (int j = 0; j < 8; j++) {
            int c = tx * 8 + j;
            float4 pj = make_float4(s[0][j], s[1][j], s[2][j], s[3][j]);
            *(float4*)&ss[c * 128 + 4 * (ty ^ tx)] = pj;
        }

        CPWAIT1();         // V(kt) landed
        __syncthreads();   // ss + vs visible

        // P @ V
        const float* vb = vs + (kt & 1) * 4096;
        #pragma unroll 2
        for (int c = 0; c < 64; c++) {
            float4 a4 = *(const float4*)&ss[c * 128 + 4 * (ty ^ ((c >> 3) & 7))];
            float a[4] = {a4.x, a4.y, a4.z, a4.w};
            ull bp[4];
            #pragma unroll
            for (int j = 0; j < 4; j++) bp[j] = *(const ull*)&vb[c * 64 + tx * 8 + 2 * j];
            #pragma unroll
            for (int i = 0; i < 4; i++) {
                ull ad; asm("mov.b64 %0, {%1, %1};" : "=l"(ad) : "f"(a[i]));
                #pragma unroll
                for (int j = 0; j < 4; j++)
                    asm("fma.rn.f32x2 %0, %1, %2, %0;" : "+l"(accO[i][j]) : "l"(ad), "l"(bp[j]));
            }
        }
        __syncthreads();   // done with ks/vs/ss this iteration
    }

    // Epilogue
    #pragma unroll
    for (int i = 0; i < 4; i++) {
        float inv_l = 1.f / l_reg[i];
        float o8[8];
        #pragma unroll
        for (int j = 0; j < 4; j++) {
            float2 p = *(float2*)&accO[i][j];
            o8[2 * j]     = p.x * inv_l;
            o8[2 * j + 1] = p.y * inv_l;
        }
        size_t base = ((size_t)(b * Sl + qt * 128 + ty * 4 + i) * Hn + h) * 64 + tx * 8;
        *(float4*)&o[base]     = *(float4*)&o8[0];
        *(float4*)&o[base + 4] = *(float4*)&o8[4];
    }
}

// ---------------------------------------------------------------------------
// Chunked delta-rule memory scan (side stream).
// ---------------------------------------------------------------------------
__global__ void memscan_kernel(const float* __restrict__ z,
                               const float* __restrict__ M_init,
                               const float* __restrict__ w_eta, const float* __restrict__ b_eta,
                               const float* __restrict__ w_alpha, const float* __restrict__ b_alpha,
                               const float* __restrict__ w_gate, const float* __restrict__ b_gate,
                               float* __restrict__ mem_out) {
    __shared__ float Ms[64][64];
    __shared__ float chs[64][64];
    __shared__ float red2[16][64];
    __shared__ float se[64], sa[64], sg[64], nrm[64];
    __shared__ float kmean[64], vt[64], diffv[64];
    __shared__ float red[256];
    __shared__ float sc_eta, sc_alpha, sc_gate, sc_scale;

    int b = blockIdx.x;
    int tid = threadIdx.x;
    int tx = tid & 15, ty = tid >> 4;

    #pragma unroll
    for (int i = 0; i < 16; i++) {
        int idx = tid + i * 256;
        Ms[idx >> 6][idx & 63] = M_init[idx];
    }
    __syncthreads();

    for (int c = 0; c < NCH; c++) {
        #pragma unroll
        for (int i = 0; i < 16; i++) {
            int idx = tid + i * 256;
            chs[idx >> 6][idx & 63] = z[((size_t)b * Sl + c * 64 + (idx >> 6)) * 64 + (idx & 63)];
        }
        __syncthreads();

        float o4[4][4] = {};
        #pragma unroll
        for (int d = 0; d < 64; d++) {
            float a0 = chs[ty*4+0][d], a1 = chs[ty*4+1][d];
            float a2 = chs[ty*4+2][d], a3 = chs[ty*4+3][d];
            float m0 = Ms[tx*4+0][d], m1 = Ms[tx*4+1][d];
            float m2 = Ms[tx*4+2][d], m3 = Ms[tx*4+3][d];
            o4[0][0] += a0*m0; o4[0][1] += a0*m1; o4[0][2] += a0*m2; o4[0][3] += a0*m3;
            o4[1][0] += a1*m0; o4[1][1] += a1*m1; o4[1][2] += a1*m2; o4[1][3] += a1*m3;
            o4[2][0] += a2*m0; o4[2][1] += a2*m1; o4[2][2] += a2*m2; o4[2][3] += a2*m3;
            o4[3][0] += a3*m0; o4[3][1] += a3*m1; o4[3][2] += a3*m2; o4[3][3] += a3*m3;
        }
        #pragma unroll
        for (int i = 0; i < 4; i++)
            #pragma unroll
            for (int j = 0; j < 4; j++)
                mem_out[((size_t)b * Sl + c * 64 + ty * 4 + i) * 64 + tx * 4 + j] = o4[i][j];
        #pragma unroll
        for (int j = 0; j < 4; j++)
            red2[ty][tx * 4 + j] = o4[0][j] + o4[1][j] + o4[2][j] + o4[3][j];
        __syncthreads();

        if (tid < 64) {
            float de = 0.f, da = 0.f, dg = 0.f, nn = 0.f;
            #pragma unroll
            for (int d = 0; d < 64; d++) {
                float x = chs[tid][d];
                de += x * w_eta[d];
                da += x * w_alpha[d];
                dg += x * w_gate[d];
                nn += x * x;
            }
            se[tid] = 0.2f / (1.f + expf(-(de + b_eta[0])));
            sa[tid] = 0.5f + 0.5f / (1.f + expf(-(da + b_alpha[0])));
            sg[tid] = 1.f / (1.f + expf(-(dg + b_gate[0])));
            nrm[tid] = fmaxf(sqrtf(nn), 1e-6f);
        }
        __syncthreads();

        if (tid < 64) {
            float s = 0.f;
            #pragma unroll
            for (int t = 0; t < 64; t++) s += chs[t][tid] / nrm[t];
            kmean[tid] = s * (1.f / 64.f);
        } else if (tid < 128) {
            int vv = tid - 64;
            float s = 0.f;
            #pragma unroll
            for (int yy = 0; yy < 16; yy++) s += red2[yy][vv];
            vt[vv] = s * (1.f / 64.f);
        } else if (tid == 128) {
            float e = 0.f, a = 0.f, g = 0.f;
            #pragma unroll
            for (int t = 0; t < 64; t++) { e += se[t]; a += sa[t]; g += sg[t]; }
            sc_eta = e * (1.f / 64.f);
            sc_alpha = a * (1.f / 64.f);
            sc_gate = g * (1.f / 64.f);
        }
        __syncthreads();

        if (tid < 64) {
            float s = 0.f;
            #pragma unroll
            for (int d = 0; d < 64; d++) s += Ms[tid][d] * kmean[d];
            diffv[tid] = vt[tid] - s;
        }
        __syncthreads();

        float eg = sc_eta * sc_gate, al = sc_alpha;
        float ss2 = 0.f;
        #pragma unroll
        for (int i = 0; i < 16; i++) {
            int idx = tid + i * 256;
            int vv = idx >> 6, d = idx & 63;
            float mn = al * Ms[vv][d] + eg * diffv[vv] * kmean[d];
            Ms[vv][d] = mn;
            ss2 += mn * mn;
        }
        red[tid] = ss2;
        __syncthreads();
        for (int st = 128; st > 0; st >>= 1) {
            if (tid < st) red[tid] += red[tid + st];
            __syncthreads();
        }
        if (tid == 0) {
            float fro = sqrtf(red[0]);
            sc_scale = fminf(1.f, 30.f / fmaxf(fro, 1e-6f));
        }
        __syncthreads();
        #pragma unroll
        for (int i = 0; i < 16; i++) {
            int idx = tid + i * 256;
            Ms[idx >> 6][idx & 63] *= sc_scale;
        }
        __syncthreads();
    }
}

// ---------------------------------------------------------------------------
extern "C" void kernel_launch(void* const* d_in, const int* in_sizes, int n_in,
                              void* d_out, int out_size) {
    const float* x       = (const float*)d_in[0];
    const float* Wq      = (const float*)d_in[1];
    const float* Wk      = (const float*)d_in[2];
    const float* Wv      = (const float*)d_in[3];
    const float* Wo      = (const float*)d_in[4];
    const float* Wmemin  = (const float*)d_in[5];
    const float* Wmemout = (const float*)d_in[6];
    const float* M_init  = (const float*)d_in[7];
    const float* w_eta   = (const float*)d_in[8];
    const float* b_eta   = (const float*)d_in[9];
    const float* w_alpha = (const float*)d_in[10];
    const float* b_alpha = (const float*)d_in[11];
    const float* w_gate  = (const float*)d_in[12];
    const float* b_gate  = (const float*)d_in[13];
    float* out = (float*)d_out;

    float *q, *k, *v, *attn, *z, *mem;
    cudaGetSymbolAddress((void**)&q, g_q);
    cudaGetSymbolAddress((void**)&k, g_k);
    cudaGetSymbolAddress((void**)&v, g_v);
    cudaGetSymbolAddress((void**)&attn, g_attn);
    cudaGetSymbolAddress((void**)&z, g_z);
    cudaGetSymbolAddress((void**)&mem, g_mem);

    static cudaStream_t s2 = nullptr;
    static cudaEvent_t evZ = nullptr, evM = nullptr;
    static int inited = 0;
    if (!inited) {
        cudaStreamCreateWithFlags(&s2, cudaStreamNonBlocking);
        cudaEventCreateWithFlags(&evZ, cudaEventDisableTiming);
        cudaEventCreateWithFlags(&evM, cudaEventDisableTiming);
        cudaFuncSetAttribute(attn_kernel,
                             cudaFuncAttributeMaxDynamicSharedMemorySize, ATTN_BYTES);
        inited = 1;
    }

    // Fused projections (q, k, v, z) — fills the whole chip.
    proj_kernel<<<dim3(25, 32), 128>>>(x, Wq, Wk, Wv, Wmemin, q, k, v, z);

    // Fork serial memscan onto side stream (depends on z).
    cudaEventRecord(evZ, 0);
    cudaStreamWaitEvent(s2, evZ, 0);
    memscan_kernel<<<Bsz, 256, 0, s2>>>(z, M_init, w_eta, b_eta, w_alpha, b_alpha,
                                        w_gate, b_gate, mem);
    cudaEventRecord(evM, s2);

    // RoPE
    rope_kernel<<<(Bsz*Sl*Hn*32 + 255)/256, 256>>>(q, Hn);
    rope_kernel<<<(Bsz*Sl*HKn*32 + 255)/256, 256>>>(k, HKn);

    // Attention
    attn_kernel<<<dim3(Sl/128, Bsz*Hn), 256, ATTN_BYTES>>>(q, k, v, attn);

    // Join memscan, then fused output GEMM
    cudaStreamWaitEvent((cudaStream_t)0, evM, 0);
    dual_gemm_kernel<<<dim3(16, 32), 128>>>(attn, Wo, Hn*HDn,
                                            mem, Wmemout, DVn, out, Dm);
}

// round 4
// speedup vs baseline: 2.6336x; 1.7049x over previous
#include <cuda_runtime.h>
#include <math.h>
#include <stdint.h>

#define Bsz 2
#define Sl  2048
#define Dm  1024
#define Hn  16
#define HKn 4
#define HDn 64
#define DKn 64
#define DVn 64
#define NCH 32
#define MS  (Bsz*Sl)

__device__ float g_q[Bsz*Sl*Hn*HDn];
__device__ float g_k[Bsz*Sl*HKn*HDn];
__device__ float g_v[Bsz*Sl*HKn*HDn];
__device__ float g_attn[Bsz*Sl*Hn*HDn];
__device__ float g_z[Bsz*Sl*DKn];
__device__ float g_mem[Bsz*Sl*DVn];

__device__ __forceinline__ uint32_t f2tf(float x) {
    uint32_t u; asm("cvt.rna.tf32.f32 %0, %1;" : "=r"(u) : "f"(x)); return u;
}

// mma.sync m16n8k8 tf32: D += A(16x8,row) * B(8x8,col)
__device__ __forceinline__ void mma8(float d[4], const uint32_t a[4], const uint32_t b[2]) {
    asm volatile(
        "mma.sync.aligned.m16n8k8.row.col.f32.tf32.tf32.f32 "
        "{%0,%1,%2,%3}, {%4,%5,%6,%7}, {%8,%9}, {%0,%1,%2,%3};"
        : "+f"(d[0]), "+f"(d[1]), "+f"(d[2]), "+f"(d[3])
        : "r"(a[0]), "r"(a[1]), "r"(a[2]), "r"(a[3]), "r"(b[0]), "r"(b[1]));
}

// ===========================================================================
// TF32 GEMM core: BM=128, BN=64, BK=16, 256 threads (8 warps, 4x2 warp grid),
// warp tile 32x32 (2 m16-tiles x 4 n8-tiles).
// As[k][m] stride 136 (conflict-free fragment loads), Bs[k][n] stride 72.
// ===========================================================================
#define AS_STR 136
#define BS_STR 72

__device__ __forceinline__ void g_load(const float* __restrict__ A,
                                       const float* __restrict__ B,
                                       int K, int N, int row0, int col0, int k0,
                                       int tid, float4 ar[2], float4& br) {
    #pragma unroll
    for (int i = 0; i < 2; i++) {
        int vec = tid + i * 256;
        int m = vec >> 2, kq = vec & 3;
        ar[i] = *(const float4*)&A[(size_t)(row0 + m) * K + k0 + kq * 4];
    }
    int kk = tid >> 4, nq = tid & 15;
    br = *(const float4*)&B[(size_t)(k0 + kk) * N + col0 + nq * 4];
}

__device__ __forceinline__ void g_sts(uint32_t* As, uint32_t* Bs, int tid,
                                      const float4 ar[2], const float4& br) {
    #pragma unroll
    for (int i = 0; i < 2; i++) {
        int vec = tid + i * 256;
        int m = vec >> 2, kq = vec & 3;
        As[(kq * 4 + 0) * AS_STR + m] = f2tf(ar[i].x);
        As[(kq * 4 + 1) * AS_STR + m] = f2tf(ar[i].y);
        As[(kq * 4 + 2) * AS_STR + m] = f2tf(ar[i].z);
        As[(kq * 4 + 3) * AS_STR + m] = f2tf(ar[i].w);
    }
    int kk = tid >> 4, nq = tid & 15;
    uint4 t;
    t.x = f2tf(br.x); t.y = f2tf(br.y); t.z = f2tf(br.z); t.w = f2tf(br.w);
    *(uint4*)&Bs[kk * BS_STR + nq * 4] = t;
}

__device__ __forceinline__ void g_mma(const uint32_t* As, const uint32_t* Bs,
                                      int lane, int wm, int wn, float d[2][4][4]) {
    #pragma unroll
    for (int ks = 0; ks < 16; ks += 8) {
        int kc = ks + (lane & 3);
        uint32_t a[2][4], b[4][2];
        #pragma unroll
        for (int mt = 0; mt < 2; mt++) {
            int r = wm * 32 + mt * 16 + (lane >> 2);
            a[mt][0] = As[kc * AS_STR + r];
            a[mt][1] = As[kc * AS_STR + r + 8];
            a[mt][2] = As[(kc + 4) * AS_STR + r];
            a[mt][3] = As[(kc + 4) * AS_STR + r + 8];
        }
        #pragma unroll
        for (int nt = 0; nt < 4; nt++) {
            int n = wn * 32 + nt * 8 + (lane >> 2);
            b[nt][0] = Bs[kc * BS_STR + n];
            b[nt][1] = Bs[(kc + 4) * BS_STR + n];
        }
        #pragma unroll
        for (int mt = 0; mt < 2; mt++)
            #pragma unroll
            for (int nt = 0; nt < 4; nt++)
                mma8(d[mt][nt], a[mt], b[nt]);
    }
}

__device__ __forceinline__ void g_epilogue(float d[2][4][4], float* __restrict__ C,
                                           int N, int row0, int col0,
                                           int lane, int wm, int wn) {
    #pragma unroll
    for (int mt = 0; mt < 2; mt++) {
        #pragma unroll
        for (int nt = 0; nt < 4; nt++) {
            int r = row0 + wm * 32 + mt * 16 + (lane >> 2);
            int cc = col0 + wn * 32 + nt * 8 + 2 * (lane & 3);
            *(float2*)&C[(size_t)r * N + cc]       = make_float2(d[mt][nt][0], d[mt][nt][1]);
            *(float2*)&C[(size_t)(r + 8) * N + cc] = make_float2(d[mt][nt][2], d[mt][nt][3]);
        }
    }
}

// ---------------------------------------------------------------------------
// Fused projection GEMM: x @ {Wq|Wk|Wv|Wmemin}. grid=(25,32), block=256.
// ---------------------------------------------------------------------------
__global__ __launch_bounds__(256)
void proj_kernel(const float* __restrict__ x,
                 const float* __restrict__ Wq, const float* __restrict__ Wk,
                 const float* __restrict__ Wv, const float* __restrict__ Wz,
                 float* __restrict__ q, float* __restrict__ kout,
                 float* __restrict__ vout, float* __restrict__ z) {
    __shared__ uint32_t As[16 * AS_STR];
    __shared__ uint32_t Bs[16 * BS_STR];
    int tid = threadIdx.x;
    int lane = tid & 31, warp = tid >> 5;
    int wm = warp >> 1, wn = warp & 1;
    int ct = blockIdx.x;
    int row0 = blockIdx.y * 128;
    const float* B; float* C; int N, col0;
    if (ct < 16)      { B = Wq; C = q;    N = 1024; col0 = ct * 64; }
    else if (ct < 20) { B = Wk; C = kout; N = 256;  col0 = (ct - 16) * 64; }
    else if (ct < 24) { B = Wv; C = vout; N = 256;  col0 = (ct - 20) * 64; }
    else              { B = Wz; C = z;    N = 64;   col0 = 0; }

    float d[2][4][4] = {};
    float4 ar[2]; float4 br;
    g_load(x, B, 1024, N, row0, col0, 0, tid, ar, br);
    for (int k0 = 0; k0 < 1024; k0 += 16) {
        g_sts(As, Bs, tid, ar, br);
        __syncthreads();
        if (k0 + 16 < 1024) g_load(x, B, 1024, N, row0, col0, k0 + 16, tid, ar, br);
        g_mma(As, Bs, lane, wm, wn, d);
        __syncthreads();
    }
    g_epilogue(d, C, N, row0, col0, lane, wm, wn);
}

// ---------------------------------------------------------------------------
// Dual GEMM: C = A1@B1 + A2@B2. grid=(16,32), block=256.
// ---------------------------------------------------------------------------
__global__ __launch_bounds__(256)
void dual_gemm_kernel(const float* __restrict__ A1, const float* __restrict__ B1, int K1,
                      const float* __restrict__ A2, const float* __restrict__ B2, int K2,
                      float* __restrict__ C, int N) {
    __shared__ uint32_t As[16 * AS_STR];
    __shared__ uint32_t Bs[16 * BS_STR];
    int tid = threadIdx.x;
    int lane = tid & 31, warp = tid >> 5;
    int wm = warp >> 1, wn = warp & 1;
    int row0 = blockIdx.y * 128, col0 = blockIdx.x * 64;
    float d[2][4][4] = {};
    float4 ar[2]; float4 br;
    #pragma unroll
    for (int ph = 0; ph < 2; ph++) {
        const float* A = ph ? A2 : A1;
        const float* B = ph ? B2 : B1;
        int K = ph ? K2 : K1;
        g_load(A, B, K, N, row0, col0, 0, tid, ar, br);
        for (int k0 = 0; k0 < K; k0 += 16) {
            g_sts(As, Bs, tid, ar, br);
            __syncthreads();
            if (k0 + 16 < K) g_load(A, B, K, N, row0, col0, k0 + 16, tid, ar, br);
            g_mma(As, Bs, lane, wm, wn, d);
            __syncthreads();
        }
    }
    g_epilogue(d, C, N, row0, col0, lane, wm, wn);
}

// ---------------------------------------------------------------------------
// RoPE in place on [B, S, nheads, 64].
// ---------------------------------------------------------------------------
__global__ void rope_kernel(float* __restrict__ t, int nheads) {
    int idx = blockIdx.x * blockDim.x + threadIdx.x;
    int total = Bsz * Sl * nheads * 32;
    if (idx >= total) return;
    int j = idx & 31;
    int h = (idx >> 5) % nheads;
    int s = ((idx >> 5) / nheads) % Sl;
    int b = idx / (32 * nheads * Sl);
    float inv = powf(500000.0f, -(float)(2 * j) / 64.0f);
    float ang = (float)s * inv;
    float c, sn;
    __sincosf(ang, &sn, &c);
    size_t base = ((size_t)(b * Sl + s) * nheads + h) * 64;
    float u1 = t[base + j], u2 = t[base + j + 32];
    t[base + j]      = u1 * c - u2 * sn;
    t[base + j + 32] = u2 * c + u1 * sn;
}

// ---------------------------------------------------------------------------
// TF32 flash attention: 128q x 64kv tiles, 256 threads (8 warps x 16 rows).
// QK and PV on tensor pipe; P relayout via shfl; V^T smem XOR-swizzled.
// ---------------------------------------------------------------------------
#define TST 68
#define ATTN_U32 ((128 + 64 + 2*64) * TST)
#define ATTN_BYTES (ATTN_U32 * 4)

__global__ __launch_bounds__(256)
void attn_kernel(const float* __restrict__ q, const float* __restrict__ k,
                 const float* __restrict__ v, float* __restrict__ o) {
    extern __shared__ uint32_t smu[];
    uint32_t* qs = smu;                 // [r:128][d:64] stride 68
    uint32_t* ks = qs + 128 * TST;      // [c:64][d:64]  stride 68
    uint32_t* vs = ks + 64 * TST;       // 2 x [d:64][c^sw:64] stride 68

    int qt = (int)gridDim.x - 1 - (int)blockIdx.x;   // longest tiles first
    int bh = blockIdx.y;
    int b = bh >> 4, h = bh & 15, kh = h >> 2;
    int tid = threadIdx.x;
    int lane = tid & 31, w = tid >> 5;
    int g = lane >> 2, c4 = lane & 3;
    int r0 = w * 16 + g;                 // fragment row (r1 = r0+8)

    // ---- load Q tile (scaled, tf32) ----
    size_t qbase = ((size_t)(b * Sl + qt * 128) * Hn + h) * 64;
    #pragma unroll
    for (int i = 0; i < 8; i++) {
        int vec = tid + i * 256;
        int r = vec >> 4, dq = vec & 15;
        float4 t = *(const float4*)&q[qbase + (size_t)r * Hn * 64 + dq * 4];
        uint4 u;
        u.x = f2tf(t.x * 0.125f); u.y = f2tf(t.y * 0.125f);
        u.z = f2tf(t.z * 0.125f); u.w = f2tf(t.w * 0.125f);
        *(uint4*)&qs[r * TST + dq * 4] = u;
    }

    size_t kvbase = ((size_t)(b * Sl) * HKn + kh) * 64;
    int ktmax = 2 * qt + 1;

    // ---- preload K(0) regs; preload+store V(0) into vs buffer 0 ----
    float4 kr[4], vr[4];
    #pragma unroll
    for (int i = 0; i < 4; i++) {
        int vec = tid + i * 256;
        int c = vec >> 4, dq = vec & 15;
        kr[i] = *(const float4*)&k[kvbase + (size_t)c * HKn * 64 + dq * 4];
        vr[i] = *(const float4*)&v[kvbase + (size_t)c * HKn * 64 + dq * 4];
    }
    #pragma unroll
    for (int i = 0; i < 4; i++) {
        int vec = tid + i * 256;
        int c = vec >> 4, dq = vec & 15;
        int sw = c ^ (dq & 7);           // ((dq*4+j)>>2)&7 == dq&7
        vs[(dq * 4 + 0) * TST + sw] = f2tf(vr[i].x);
        vs[(dq * 4 + 1) * TST + sw] = f2tf(vr[i].y);
        vs[(dq * 4 + 2) * TST + sw] = f2tf(vr[i].z);
        vs[(dq * 4 + 3) * TST + sw] = f2tf(vr[i].w);
    }

    float m0 = -3e38f, m1 = -3e38f, l0 = 0.f, l1 = 0.f;
    float accO[8][4] = {};

    for (int kt = 0; kt <= ktmax; kt++) {
        // ---- store K(kt) from regs ----
        #pragma unroll
        for (int i = 0; i < 4; i++) {
            int vec = tid + i * 256;
            int c = vec >> 4, dq = vec & 15;
            uint4 u;
            u.x = f2tf(kr[i].x); u.y = f2tf(kr[i].y);
            u.z = f2tf(kr[i].z); u.w = f2tf(kr[i].w);
            *(uint4*)&ks[c * TST + dq * 4] = u;
        }
        __syncthreads();

        // prefetch K(kt+1)
        if (kt < ktmax) {
            size_t base = kvbase + (size_t)(kt + 1) * 64 * HKn * 64;
            #pragma unroll
            for (int i = 0; i < 4; i++) {
                int vec = tid + i * 256;
                int c = vec >> 4, dq = vec & 15;
                kr[i] = *(const float4*)&k[base + (size_t)c * HKn * 64 + dq * 4];
            }
        }

        // ---- QK^T ----
        float sc[8][4] = {};
        #pragma unroll
        for (int t8 = 0; t8 < 8; t8++) {
            int kc = t8 * 8 + c4;
            uint32_t a[4];
            a[0] = qs[r0 * TST + kc];
            a[1] = qs[(r0 + 8) * TST + kc];
            a[2] = qs[r0 * TST + kc + 4];
            a[3] = qs[(r0 + 8) * TST + kc + 4];
            #pragma unroll
            for (int nt = 0; nt < 8; nt++) {
                int n = nt * 8 + g;
                uint32_t bb[2] = { ks[n * TST + kc], ks[n * TST + kc + 4] };
                mma8(sc[nt], a, bb);
            }
        }

        // ---- causal mask ----
        if (kt >= 2 * qt) {
            int rg0 = qt * 128 + r0, rg1 = rg0 + 8;
            #pragma unroll
            for (int nt = 0; nt < 8; nt++) {
                int cg = kt * 64 + nt * 8 + 2 * c4;
                if (cg > rg0)     sc[nt][0] = -3e38f;
                if (cg + 1 > rg0) sc[nt][1] = -3e38f;
                if (cg > rg1)     sc[nt][2] = -3e38f;
                if (cg + 1 > rg1) sc[nt][3] = -3e38f;
            }
        }

        // ---- online softmax (rows r0, r0+8; 4-lane groups share a row) ----
        float mx0 = m0, mx1 = m1;
        #pragma unroll
        for (int nt = 0; nt < 8; nt++) {
            mx0 = fmaxf(mx0, fmaxf(sc[nt][0], sc[nt][1]));
            mx1 = fmaxf(mx1, fmaxf(sc[nt][2], sc[nt][3]));
        }
        mx0 = fmaxf(mx0, __shfl_xor_sync(0xffffffffu, mx0, 1));
        mx0 = fmaxf(mx0, __shfl_xor_sync(0xffffffffu, mx0, 2));
        mx1 = fmaxf(mx1, __shfl_xor_sync(0xffffffffu, mx1, 1));
        mx1 = fmaxf(mx1, __shfl_xor_sync(0xffffffffu, mx1, 2));
        float f0 = __expf(m0 - mx0), f1 = __expf(m1 - mx1);
        m0 = mx0; m1 = mx1;
        float sum0 = 0.f, sum1 = 0.f;
        #pragma unroll
        for (int nt = 0; nt < 8; nt++) {
            sc[nt][0] = __expf(sc[nt][0] - mx0); sum0 += sc[nt][0];
            sc[nt][1] = __expf(sc[nt][1] - mx0); sum0 += sc[nt][1];
            sc[nt][2] = __expf(sc[nt][2] - mx1); sum1 += sc[nt][2];
            sc[nt][3] = __expf(sc[nt][3] - mx1); sum1 += sc[nt][3];
        }
        sum0 += __shfl_xor_sync(0xffffffffu, sum0, 1);
        sum0 += __shfl_xor_sync(0xffffffffu, sum0, 2);
        sum1 += __shfl_xor_sync(0xffffffffu, sum1, 1);
        sum1 += __shfl_xor_sync(0xffffffffu, sum1, 2);
        l0 = l0 * f0 + sum0;
        l1 = l1 * f1 + sum1;
        #pragma unroll
        for (int nt = 0; nt < 8; nt++) {
            accO[nt][0] *= f0; accO[nt][1] *= f0;
            accO[nt][2] *= f1; accO[nt][3] *= f1;
        }

        // prefetch V(kt+1)
        if (kt < ktmax) {
            size_t base = kvbase + (size_t)(kt + 1) * 64 * HKn * 64;
            #pragma unroll
            for (int i = 0; i < 4; i++) {
                int vec = tid + i * 256;
                int c = vec >> 4, dq = vec & 15;
                vr[i] = *(const float4*)&v[base + (size_t)c * HKn * 64 + dq * 4];
            }
        }

        // ---- P @ V (A-frags from sc via shfl) ----
        const uint32_t* vb = vs + (kt & 1) * 64 * TST;
        int src0 = (lane & ~3) | (c4 >> 1);
        int src1 = src0 + 2;
        bool odd = c4 & 1;
        #pragma unroll
        for (int t = 0; t < 8; t++) {
            float v00 = __shfl_sync(0xffffffffu, sc[t][0], src0);
            float v01 = __shfl_sync(0xffffffffu, sc[t][1], src0);
            float v10 = __shfl_sync(0xffffffffu, sc[t][0], src1);
            float v11 = __shfl_sync(0xffffffffu, sc[t][1], src1);
            float v20 = __shfl_sync(0xffffffffu, sc[t][2], src0);
            float v21 = __shfl_sync(0xffffffffu, sc[t][3], src0);
            float v30 = __shfl_sync(0xffffffffu, sc[t][2], src1);
            float v31 = __shfl_sync(0xffffffffu, sc[t][3], src1);
            uint32_t a[4];
            a[0] = f2tf(odd ? v01 : v00);   // (r0,   c)
            a[1] = f2tf(odd ? v21 : v20);   // (r0+8, c)
            a[2] = f2tf(odd ? v11 : v10);   // (r0,   c+4)
            a[3] = f2tf(odd ? v31 : v30);   // (r0+8, c+4)
            int k0i = t * 8 + c4;
            #pragma unroll
            for (int nt = 0; nt < 8; nt++) {
                int dcol = nt * 8 + g;
                int sw = (dcol >> 2) & 7;
                uint32_t bb[2] = { vb[dcol * TST + (k0i ^ sw)],
                                   vb[dcol * TST + ((k0i + 4) ^ sw)] };
                mma8(accO[nt], a, bb);
            }
        }

        // ---- store V(kt+1) into other buffer ----
        if (kt < ktmax) {
            uint32_t* vn = vs + ((kt + 1) & 1) * 64 * TST;
            #pragma unroll
            for (int i = 0; i < 4; i++) {
                int vec = tid + i * 256;
                int c = vec >> 4, dq = vec & 15;
                int sw = c ^ (dq & 7);
                vn[(dq * 4 + 0) * TST + sw] = f2tf(vr[i].x);
                vn[(dq * 4 + 1) * TST + sw] = f2tf(vr[i].y);
                vn[(dq * 4 + 2) * TST + sw] = f2tf(vr[i].z);
                vn[(dq * 4 + 3) * TST + sw] = f2tf(vr[i].w);
            }
        }
        __syncthreads();
    }

    // ---- epilogue ----
    float il0 = 1.f / l0, il1 = 1.f / l1;
    size_t ob0 = ((size_t)(b * Sl + qt * 128 + r0) * Hn + h) * 64;
    size_t ob1 = ((size_t)(b * Sl + qt * 128 + r0 + 8) * Hn + h) * 64;
    #pragma unroll
    for (int nt = 0; nt < 8; nt++) {
        int dcol = nt * 8 + 2 * c4;
        *(float2*)&o[ob0 + dcol] = make_float2(accO[nt][0] * il0, accO[nt][1] * il0);
        *(float2*)&o[ob1 + dcol] = make_float2(accO[nt][2] * il1, accO[nt][3] * il1);
    }
}

// ---------------------------------------------------------------------------
// Chunked delta-rule memory scan (side stream).
// ---------------------------------------------------------------------------
__global__ void memscan_kernel(const float* __restrict__ z,
                               const float* __restrict__ M_init,
                               const float* __restrict__ w_eta, const float* __restrict__ b_eta,
                               const float* __restrict__ w_alpha, const float* __restrict__ b_alpha,
                               const float* __restrict__ w_gate, const float* __restrict__ b_gate,
                               float* __restrict__ mem_out) {
    __shared__ float Ms[64][64];
    __shared__ float chs[64][64];
    __shared__ float red2[16][64];
    __shared__ float se[64], sa[64], sg[64], nrm[64];
    __shared__ float kmean[64], vt[64], diffv[64];
    __shared__ float red[256];
    __shared__ float sc_eta, sc_alpha, sc_gate, sc_scale;

    int b = blockIdx.x;
    int tid = threadIdx.x;
    int tx = tid & 15, ty = tid >> 4;

    #pragma unroll
    for (int i = 0; i < 16; i++) {
        int idx = tid + i * 256;
        Ms[idx >> 6][idx & 63] = M_init[idx];
    }
    __syncthreads();

    for (int c = 0; c < NCH; c++) {
        #pragma unroll
        for (int i = 0; i < 16; i++) {
            int idx = tid + i * 256;
            chs[idx >> 6][idx & 63] = z[((size_t)b * Sl + c * 64 + (idx >> 6)) * 64 + (idx & 63)];
        }
        __syncthreads();

        float o4[4][4] = {};
        #pragma unroll
        for (int d = 0; d < 64; d++) {
            float a0 = chs[ty*4+0][d], a1 = chs[ty*4+1][d];
            float a2 = chs[ty*4+2][d], a3 = chs[ty*4+3][d];
            float m0 = Ms[tx*4+0][d], m1 = Ms[tx*4+1][d];
            float m2 = Ms[tx*4+2][d], m3 = Ms[tx*4+3][d];
            o4[0][0] += a0*m0; o4[0][1] += a0*m1; o4[0][2] += a0*m2; o4[0][3] += a0*m3;
            o4[1][0] += a1*m0; o4[1][1] += a1*m1; o4[1][2] += a1*m2; o4[1][3] += a1*m3;
            o4[2][0] += a2*m0; o4[2][1] += a2*m1; o4[2][2] += a2*m2; o4[2][3] += a2*m3;
            o4[3][0] += a3*m0; o4[3][1] += a3*m1; o4[3][2] += a3*m2; o4[3][3] += a3*m3;
        }
        #pragma unroll
        for (int i = 0; i < 4; i++)
            #pragma unroll
            for (int j = 0; j < 4; j++)
                mem_out[((size_t)b * Sl + c * 64 + ty * 4 + i) * 64 + tx * 4 + j] = o4[i][j];
        #pragma unroll
        for (int j = 0; j < 4; j++)
            red2[ty][tx * 4 + j] = o4[0][j] + o4[1][j] + o4[2][j] + o4[3][j];
        __syncthreads();

        if (tid < 64) {
            float de = 0.f, da = 0.f, dg = 0.f, nn = 0.f;
            #pragma unroll
            for (int d = 0; d < 64; d++) {
                float x = chs[tid][d];
                de += x * w_eta[d];
                da += x * w_alpha[d];
                dg += x * w_gate[d];
                nn += x * x;
            }
            se[tid] = 0.2f / (1.f + expf(-(de + b_eta[0])));
            sa[tid] = 0.5f + 0.5f / (1.f + expf(-(da + b_alpha[0])));
            sg[tid] = 1.f / (1.f + expf(-(dg + b_gate[0])));
            nrm[tid] = fmaxf(sqrtf(nn), 1e-6f);
        }
        __syncthreads();

        if (tid < 64) {
            float s = 0.f;
            #pragma unroll
            for (int t = 0; t < 64; t++) s += chs[t][tid] / nrm[t];
            kmean[tid] = s * (1.f / 64.f);
        } else if (tid < 128) {
            int vv = tid - 64;
            float s = 0.f;
            #pragma unroll
            for (int yy = 0; yy < 16; yy++) s += red2[yy][vv];
            vt[vv] = s * (1.f / 64.f);
        } else if (tid == 128) {
            float e = 0.f, a = 0.f, gg = 0.f;
            #pragma unroll
            for (int t = 0; t < 64; t++) { e += se[t]; a += sa[t]; gg += sg[t]; }
            sc_eta = e * (1.f / 64.f);
            sc_alpha = a * (1.f / 64.f);
            sc_gate = gg * (1.f / 64.f);
        }
        __syncthreads();

        if (tid < 64) {
            float s = 0.f;
            #pragma unroll
            for (int d = 0; d < 64; d++) s += Ms[tid][d] * kmean[d];
            diffv[tid] = vt[tid] - s;
        }
        __syncthreads();

        float eg = sc_eta * sc_gate, al = sc_alpha;
        float ss2 = 0.f;
        #pragma unroll
        for (int i = 0; i < 16; i++) {
            int idx = tid + i * 256;
            int vv = idx >> 6, d = idx & 63;
            float mn = al * Ms[vv][d] + eg * diffv[vv] * kmean[d];
            Ms[vv][d] = mn;
            ss2 += mn * mn;
        }
        red[tid] = ss2;
        __syncthreads();
        for (int st = 128; st > 0; st >>= 1) {
            if (tid < st) red[tid] += red[tid + st];
            __syncthreads();
        }
        if (tid == 0) {
            float fro = sqrtf(red[0]);
            sc_scale = fminf(1.f, 30.f / fmaxf(fro, 1e-6f));
        }
        __syncthreads();
        #pragma unroll
        for (int i = 0; i < 16; i++) {
            int idx = tid + i * 256;
            Ms[idx >> 6][idx & 63] *= sc_scale;
        }
        __syncthreads();
    }
}

// ---------------------------------------------------------------------------
extern "C" void kernel_launch(void* const* d_in, const int* in_sizes, int n_in,
                              void* d_out, int out_size) {
    const float* x       = (const float*)d_in[0];
    const float* Wq      = (const float*)d_in[1];
    const float* Wk      = (const float*)d_in[2];
    const float* Wv      = (const float*)d_in[3];
    const float* Wo      = (const float*)d_in[4];
    const float* Wmemin  = (const float*)d_in[5];
    const float* Wmemout = (const float*)d_in[6];
    const float* M_init  = (const float*)d_in[7];
    const float* w_eta   = (const float*)d_in[8];
    const float* b_eta   = (const float*)d_in[9];
    const float* w_alpha = (const float*)d_in[10];
    const float* b_alpha = (const float*)d_in[11];
    const float* w_gate  = (const float*)d_in[12];
    const float* b_gate  = (const float*)d_in[13];
    float* out = (float*)d_out;

    float *q, *k, *v, *attn, *z, *mem;
    cudaGetSymbolAddress((void**)&q, g_q);
    cudaGetSymbolAddress((void**)&k, g_k);
    cudaGetSymbolAddress((void**)&v, g_v);
    cudaGetSymbolAddress((void**)&attn, g_attn);
    cudaGetSymbolAddress((void**)&z, g_z);
    cudaGetSymbolAddress((void**)&mem, g_mem);

    static cudaStream_t s2 = nullptr;
    static cudaEvent_t evZ = nullptr, evM = nullptr;
    static int inited = 0;
    if (!inited) {
        cudaStreamCreateWithFlags(&s2, cudaStreamNonBlocking);
        cudaEventCreateWithFlags(&evZ, cudaEventDisableTiming);
        cudaEventCreateWithFlags(&evM, cudaEventDisableTiming);
        cudaFuncSetAttribute(attn_kernel,
                             cudaFuncAttributeMaxDynamicSharedMemorySize, ATTN_BYTES);
        inited = 1;
    }

    // Fused projections (q, k, v, z)
    proj_kernel<<<dim3(25, 32), 256>>>(x, Wq, Wk, Wv, Wmemin, q, k, v, z);

    // Fork serial memscan onto side stream (depends on z)
    cudaEventRecord(evZ, 0);
    cudaStreamWaitEvent(s2, evZ, 0);
    memscan_kernel<<<Bsz, 256, 0, s2>>>(z, M_init, w_eta, b_eta, w_alpha, b_alpha,
                                        w_gate, b_gate, mem);
    cudaEventRecord(evM, s2);

    // RoPE
    rope_kernel<<<(Bsz*Sl*Hn*32 + 255)/256, 256>>>(q, Hn);
    rope_kernel<<<(Bsz*Sl*HKn*32 + 255)/256, 256>>>(k, HKn);

    // Attention
    attn_kernel<<<dim3(Sl/128, Bsz*Hn), 256, ATTN_BYTES>>>(q, k, v, attn);

    // Join memscan, then fused output GEMM
    cudaStreamWaitEvent((cudaStream_t)0, evM, 0);
    dual_gemm_kernel<<<dim3(16, 32), 256>>>(attn, Wo, Hn*HDn,
                                            mem, Wmemout, DVn, out, Dm);
}

// round 5
// speedup vs baseline: 2.6800x; 1.0176x over previous
#include <cuda_runtime.h>
#include <math.h>
#include <stdint.h>

#define Bsz 2
#define Sl  2048
#define Dm  1024
#define Hn  16
#define HKn 4
#define HDn 64
#define DKn 64
#define DVn 64
#define NCH 32
#define MS  (Bsz*Sl)

__device__ float g_q[Bsz*Sl*Hn*HDn];
__device__ float g_k[Bsz*Sl*HKn*HDn];
__device__ float g_v[Bsz*Sl*HKn*HDn];
__device__ float g_attn[Bsz*Sl*Hn*HDn];
__device__ float g_z[Bsz*Sl*DKn];
__device__ float g_mem[Bsz*Sl*DVn];

__device__ __forceinline__ uint32_t f2tf(float x) {
    uint32_t u; asm("cvt.rna.tf32.f32 %0, %1;" : "=r"(u) : "f"(x)); return u;
}

__device__ __forceinline__ unsigned su32(const void* p) {
    unsigned a;
    asm("{.reg .u64 t; cvta.to.shared.u64 t, %1; cvt.u32.u64 %0, t;}" : "=r"(a) : "l"(p));
    return a;
}
#define CP16(dst, src) asm volatile("cp.async.ca.shared.global [%0], [%1], 16;" :: "r"(dst), "l"(src))
#define CPCOMMIT()     asm volatile("cp.async.commit_group;")
#define CPWAITALL()    asm volatile("cp.async.wait_group 0;")

// mma.sync m16n8k8 tf32: D += A(16x8,row) * B(8x8,col)
__device__ __forceinline__ void mma8(float d[4], const uint32_t a[4], const uint32_t b[2]) {
    asm volatile(
        "mma.sync.aligned.m16n8k8.row.col.f32.tf32.tf32.f32 "
        "{%0,%1,%2,%3}, {%4,%5,%6,%7}, {%8,%9}, {%0,%1,%2,%3};"
        : "+f"(d[0]), "+f"(d[1]), "+f"(d[2]), "+f"(d[3])
        : "r"(a[0]), "r"(a[1]), "r"(a[2]), "r"(a[3]), "r"(b[0]), "r"(b[1]));
}

// ===========================================================================
// TF32 GEMM core: BM=128, BN=64, BK=16, 256 threads (8 warps, 4x2 warp grid),
// warp tile 32x32. Double-buffered smem, 1 sync per BK step.
// ===========================================================================
#define AS_STR 136
#define BS_STR 72

__device__ __forceinline__ void g_load(const float* __restrict__ A,
                                       const float* __restrict__ B,
                                       int K, int N, int row0, int col0, int k0,
                                       int tid, float4 ar[2], float4& br) {
    #pragma unroll
    for (int i = 0; i < 2; i++) {
        int vec = tid + i * 256;
        int m = vec >> 2, kq = vec & 3;
        ar[i] = *(const float4*)&A[(size_t)(row0 + m) * K + k0 + kq * 4];
    }
    int kk = tid >> 4, nq = tid & 15;
    br = *(const float4*)&B[(size_t)(k0 + kk) * N + col0 + nq * 4];
}

__device__ __forceinline__ void g_sts(uint32_t* As, uint32_t* Bs, int tid,
                                      const float4 ar[2], const float4& br) {
    #pragma unroll
    for (int i = 0; i < 2; i++) {
        int vec = tid + i * 256;
        int m = vec >> 2, kq = vec & 3;
        As[(kq * 4 + 0) * AS_STR + m] = f2tf(ar[i].x);
        As[(kq * 4 + 1) * AS_STR + m] = f2tf(ar[i].y);
        As[(kq * 4 + 2) * AS_STR + m] = f2tf(ar[i].z);
        As[(kq * 4 + 3) * AS_STR + m] = f2tf(ar[i].w);
    }
    int kk = tid >> 4, nq = tid & 15;
    uint4 t;
    t.x = f2tf(br.x); t.y = f2tf(br.y); t.z = f2tf(br.z); t.w = f2tf(br.w);
    *(uint4*)&Bs[kk * BS_STR + nq * 4] = t;
}

__device__ __forceinline__ void g_mma(const uint32_t* As, const uint32_t* Bs,
                                      int lane, int wm, int wn, float d[2][4][4]) {
    #pragma unroll
    for (int ks = 0; ks < 16; ks += 8) {
        int kc = ks + (lane & 3);
        uint32_t a[2][4], b[4][2];
        #pragma unroll
        for (int mt = 0; mt < 2; mt++) {
            int r = wm * 32 + mt * 16 + (lane >> 2);
            a[mt][0] = As[kc * AS_STR + r];
            a[mt][1] = As[kc * AS_STR + r + 8];
            a[mt][2] = As[(kc + 4) * AS_STR + r];
            a[mt][3] = As[(kc + 4) * AS_STR + r + 8];
        }
        #pragma unroll
        for (int nt = 0; nt < 4; nt++) {
            int n = wn * 32 + nt * 8 + (lane >> 2);
            b[nt][0] = Bs[kc * BS_STR + n];
            b[nt][1] = Bs[(kc + 4) * BS_STR + n];
        }
        #pragma unroll
        for (int mt = 0; mt < 2; mt++)
            #pragma unroll
            for (int nt = 0; nt < 4; nt++)
                mma8(d[mt][nt], a[mt], b[nt]);
    }
}

__device__ __forceinline__ void g_epilogue(float d[2][4][4], float* __restrict__ C,
                                           int N, int row0, int col0,
                                           int lane, int wm, int wn) {
    #pragma unroll
    for (int mt = 0; mt < 2; mt++) {
        #pragma unroll
        for (int nt = 0; nt < 4; nt++) {
            int r = row0 + wm * 32 + mt * 16 + (lane >> 2);
            int cc = col0 + wn * 32 + nt * 8 + 2 * (lane & 3);
            *(float2*)&C[(size_t)r * N + cc]       = make_float2(d[mt][nt][0], d[mt][nt][1]);
            *(float2*)&C[(size_t)(r + 8) * N + cc] = make_float2(d[mt][nt][2], d[mt][nt][3]);
        }
    }
}

// ---------------------------------------------------------------------------
// Fused projection GEMM: x @ {Wq|Wk|Wv|Wmemin}. grid=(25,32), block=256.
// ---------------------------------------------------------------------------
__global__ __launch_bounds__(256)
void proj_kernel(const float* __restrict__ x,
                 const float* __restrict__ Wq, const float* __restrict__ Wk,
                 const float* __restrict__ Wv, const float* __restrict__ Wz,
                 float* __restrict__ q, float* __restrict__ kout,
                 float* __restrict__ vout, float* __restrict__ z) {
    __shared__ uint32_t As[2][16 * AS_STR];
    __shared__ uint32_t Bs[2][16 * BS_STR];
    int tid = threadIdx.x;
    int lane = tid & 31, warp = tid >> 5;
    int wm = warp >> 1, wn = warp & 1;
    int ct = blockIdx.x;
    int row0 = blockIdx.y * 128;
    const float* B; float* C; int N, col0;
    if (ct < 16)      { B = Wq; C = q;    N = 1024; col0 = ct * 64; }
    else if (ct < 20) { B = Wk; C = kout; N = 256;  col0 = (ct - 16) * 64; }
    else if (ct < 24) { B = Wv; C = vout; N = 256;  col0 = (ct - 20) * 64; }
    else              { B = Wz; C = z;    N = 64;   col0 = 0; }

    float d[2][4][4] = {};
    float4 ar[2]; float4 br;
    g_load(x, B, 1024, N, row0, col0, 0, tid, ar, br);
    g_sts(As[0], Bs[0], tid, ar, br);
    __syncthreads();
    for (int k0 = 0; k0 < 1024; k0 += 16) {
        int cur = (k0 >> 4) & 1;
        if (k0 + 16 < 1024) g_load(x, B, 1024, N, row0, col0, k0 + 16, tid, ar, br);
        g_mma(As[cur], Bs[cur], lane, wm, wn, d);
        if (k0 + 16 < 1024) g_sts(As[cur ^ 1], Bs[cur ^ 1], tid, ar, br);
        __syncthreads();
    }
    g_epilogue(d, C, N, row0, col0, lane, wm, wn);
}

// ---------------------------------------------------------------------------
// Dual GEMM: C = A1@B1 + A2@B2. grid=(16,32), block=256.
// ---------------------------------------------------------------------------
__global__ __launch_bounds__(256)
void dual_gemm_kernel(const float* __restrict__ A1, const float* __restrict__ B1, int K1,
                      const float* __restrict__ A2, const float* __restrict__ B2, int K2,
                      float* __restrict__ C, int N) {
    __shared__ uint32_t As[2][16 * AS_STR];
    __shared__ uint32_t Bs[2][16 * BS_STR];
    int tid = threadIdx.x;
    int lane = tid & 31, warp = tid >> 5;
    int wm = warp >> 1, wn = warp & 1;
    int row0 = blockIdx.y * 128, col0 = blockIdx.x * 64;
    float d[2][4][4] = {};
    float4 ar[2]; float4 br;
    #pragma unroll
    for (int ph = 0; ph < 2; ph++) {
        const float* A = ph ? A2 : A1;
        const float* B = ph ? B2 : B1;
        int K = ph ? K2 : K1;
        g_load(A, B, K, N, row0, col0, 0, tid, ar, br);
        g_sts(As[0], Bs[0], tid, ar, br);
        __syncthreads();
        for (int k0 = 0; k0 < K; k0 += 16) {
            int cur = (k0 >> 4) & 1;
            if (k0 + 16 < K) g_load(A, B, K, N, row0, col0, k0 + 16, tid, ar, br);
            g_mma(As[cur], Bs[cur], lane, wm, wn, d);
            if (k0 + 16 < K) g_sts(As[cur ^ 1], Bs[cur ^ 1], tid, ar, br);
            __syncthreads();
        }
    }
    g_epilogue(d, C, N, row0, col0, lane, wm, wn);
}

// ---------------------------------------------------------------------------
// RoPE in place on [B, S, nheads, 64].
// ---------------------------------------------------------------------------
__global__ void rope_kernel(float* __restrict__ t, int nheads) {
    int idx = blockIdx.x * blockDim.x + threadIdx.x;
    int total = Bsz * Sl * nheads * 32;
    if (idx >= total) return;
    int j = idx & 31;
    int h = (idx >> 5) % nheads;
    int s = ((idx >> 5) / nheads) % Sl;
    int b = idx / (32 * nheads * Sl);
    float inv = powf(500000.0f, -(float)(2 * j) / 64.0f);
    float ang = (float)s * inv;
    float c, sn;
    __sincosf(ang, &sn, &c);
    size_t base = ((size_t)(b * Sl + s) * nheads + h) * 64;
    float u1 = t[base + j], u2 = t[base + j + 32];
    t[base + j]      = u1 * c - u2 * sn;
    t[base + j + 32] = u2 * c + u1 * sn;
}

// ---------------------------------------------------------------------------
// TF32 flash attention: 128q x 64kv tiles, 256 threads (8 warps x 16 rows).
// K/V double-buffered raw fp32 via cp.async (natural [c][d] layout = mma B
// fragment layout). cvt to tf32 at fragment load. One __syncthreads per tile.
// ---------------------------------------------------------------------------
#define QST 68
#define KST 68
#define VST 72
#define ATTN_WORDS (128*QST + 2*64*KST + 2*64*VST)
#define ATTN_BYTES (ATTN_WORDS * 4)

__global__ __launch_bounds__(256, 2)
void attn_kernel(const float* __restrict__ q, const float* __restrict__ k,
                 const float* __restrict__ v, float* __restrict__ o) {
    extern __shared__ float smf[];
    uint32_t* qs = (uint32_t*)smf;          // [r:128][d:64] tf32, stride 68
    float* ks = smf + 128 * QST;            // 2 x [c:64][d:64] raw, stride 68
    float* vs = ks + 2 * 64 * KST;          // 2 x [c:64][d:64] raw, stride 72

    int qt = (int)gridDim.x - 1 - (int)blockIdx.x;   // longest tiles first
    int bh = blockIdx.y;
    int b = bh >> 4, h = bh & 15, kh = h >> 2;
    int tid = threadIdx.x;
    int lane = tid & 31, w = tid >> 5;
    int g = lane >> 2, c4 = lane & 3;
    int r0 = w * 16 + g;

    // ---- load Q tile (scaled, tf32) ----
    size_t qbase = ((size_t)(b * Sl + qt * 128) * Hn + h) * 64;
    #pragma unroll
    for (int i = 0; i < 8; i++) {
        int vec = tid + i * 256;
        int r = vec >> 4, dq = vec & 15;
        float4 t = *(const float4*)&q[qbase + (size_t)r * Hn * 64 + dq * 4];
        uint4 u;
        u.x = f2tf(t.x * 0.125f); u.y = f2tf(t.y * 0.125f);
        u.z = f2tf(t.z * 0.125f); u.w = f2tf(t.w * 0.125f);
        *(uint4*)&qs[r * QST + dq * 4] = u;
    }

    size_t kvbase = ((size_t)(b * Sl) * HKn + kh) * 64;
    int ktmax = 2 * qt + 1;

    // ---- prologue: cp.async K0,V0 into buffer 0 ----
    {
        unsigned kd = su32(ks), vd = su32(vs);
        #pragma unroll
        for (int i = 0; i < 4; i++) {
            int vec = tid + i * 256;
            int c = vec >> 4, dq = vec & 15;
            CP16(kd + (unsigned)((c * KST + dq * 4) * 4),
                 &k[kvbase + (size_t)c * HKn * 64 + dq * 4]);
            CP16(vd + (unsigned)((c * VST + dq * 4) * 4),
                 &v[kvbase + (size_t)c * HKn * 64 + dq * 4]);
        }
        CPCOMMIT();
    }

    float m0 = -1e30f, m1 = -1e30f, l0 = 0.f, l1 = 0.f;
    float accO[8][4] = {};
    CPWAITALL();
    __syncthreads();

    for (int kt = 0; kt <= ktmax; kt++) {
        const float* kb = ks + (kt & 1) * 64 * KST;
        const float* vb = vs + (kt & 1) * 64 * VST;

        // issue next K/V loads into the other buffer
        if (kt < ktmax) {
            unsigned kd = su32(ks + ((kt + 1) & 1) * 64 * KST);
            unsigned vd = su32(vs + ((kt + 1) & 1) * 64 * VST);
            size_t base = kvbase + (size_t)(kt + 1) * 64 * HKn * 64;
            #pragma unroll
            for (int i = 0; i < 4; i++) {
                int vec = tid + i * 256;
                int c = vec >> 4, dq = vec & 15;
                CP16(kd + (unsigned)((c * KST + dq * 4) * 4),
                     &k[base + (size_t)c * HKn * 64 + dq * 4]);
                CP16(vd + (unsigned)((c * VST + dq * 4) * 4),
                     &v[base + (size_t)c * HKn * 64 + dq * 4]);
            }
            CPCOMMIT();
        }

        // ---- QK^T ----
        float sc[8][4] = {};
        #pragma unroll
        for (int t8 = 0; t8 < 8; t8++) {
            int kc = t8 * 8 + c4;
            uint32_t a[4];
            a[0] = qs[r0 * QST + kc];
            a[1] = qs[(r0 + 8) * QST + kc];
            a[2] = qs[r0 * QST + kc + 4];
            a[3] = qs[(r0 + 8) * QST + kc + 4];
            #pragma unroll
            for (int nt = 0; nt < 8; nt++) {
                int n = nt * 8 + g;
                uint32_t bb[2] = { f2tf(kb[n * KST + kc]), f2tf(kb[n * KST + kc + 4]) };
                mma8(sc[nt], a, bb);
            }
        }

        // ---- causal mask ----
        if (kt >= 2 * qt) {
            int rg0 = qt * 128 + r0, rg1 = rg0 + 8;
            #pragma unroll
            for (int nt = 0; nt < 8; nt++) {
                int cg = kt * 64 + nt * 8 + 2 * c4;
                if (cg > rg0)     sc[nt][0] = -1e30f;
                if (cg + 1 > rg0) sc[nt][1] = -1e30f;
                if (cg > rg1)     sc[nt][2] = -1e30f;
                if (cg + 1 > rg1) sc[nt][3] = -1e30f;
            }
        }

        // ---- online softmax (rows r0, r0+8; 4-lane groups share a row) ----
        float mx0 = m0, mx1 = m1;
        #pragma unroll
        for (int nt = 0; nt < 8; nt++) {
            mx0 = fmaxf(mx0, fmaxf(sc[nt][0], sc[nt][1]));
            mx1 = fmaxf(mx1, fmaxf(sc[nt][2], sc[nt][3]));
        }
        mx0 = fmaxf(mx0, __shfl_xor_sync(0xffffffffu, mx0, 1));
        mx0 = fmaxf(mx0, __shfl_xor_sync(0xffffffffu, mx0, 2));
        mx1 = fmaxf(mx1, __shfl_xor_sync(0xffffffffu, mx1, 1));
        mx1 = fmaxf(mx1, __shfl_xor_sync(0xffffffffu, mx1, 2));
        float f0 = __expf(m0 - mx0), f1 = __expf(m1 - mx1);
        m0 = mx0; m1 = mx1;
        float sum0 = 0.f, sum1 = 0.f;
        #pragma unroll
        for (int nt = 0; nt < 8; nt++) {
            sc[nt][0] = __expf(sc[nt][0] - mx0); sum0 += sc[nt][0];
            sc[nt][1] = __expf(sc[nt][1] - mx0); sum0 += sc[nt][1];
            sc[nt][2] = __expf(sc[nt][2] - mx1); sum1 += sc[nt][2];
            sc[nt][3] = __expf(sc[nt][3] - mx1); sum1 += sc[nt][3];
        }
        sum0 += __shfl_xor_sync(0xffffffffu, sum0, 1);
        sum0 += __shfl_xor_sync(0xffffffffu, sum0, 2);
        sum1 += __shfl_xor_sync(0xffffffffu, sum1, 1);
        sum1 += __shfl_xor_sync(0xffffffffu, sum1, 2);
        l0 = l0 * f0 + sum0;
        l1 = l1 * f1 + sum1;
        #pragma unroll
        for (int nt = 0; nt < 8; nt++) {
            accO[nt][0] *= f0; accO[nt][1] *= f0;
            accO[nt][2] *= f1; accO[nt][3] *= f1;
        }

        // ---- P @ V (A-frags from sc via shfl; B from natural-layout vs) ----
        int src0 = (lane & ~3) | (c4 >> 1);
        int src1 = src0 + 2;
        bool odd = c4 & 1;
        #pragma unroll
        for (int t = 0; t < 8; t++) {
            float v00 = __shfl_sync(0xffffffffu, sc[t][0], src0);
            float v01 = __shfl_sync(0xffffffffu, sc[t][1], src0);
            float v10 = __shfl_sync(0xffffffffu, sc[t][0], src1);
            float v11 = __shfl_sync(0xffffffffu, sc[t][1], src1);
            float v20 = __shfl_sync(0xffffffffu, sc[t][2], src0);
            float v21 = __shfl_sync(0xffffffffu, sc[t][3], src0);
            float v30 = __shfl_sync(0xffffffffu, sc[t][2], src1);
            float v31 = __shfl_sync(0xffffffffu, sc[t][3], src1);
            uint32_t a[4];
            a[0] = f2tf(odd ? v01 : v00);   // (r0,   c)
            a[1] = f2tf(odd ? v21 : v20);   // (r0+8, c)
            a[2] = f2tf(odd ? v11 : v10);   // (r0,   c+4)
            a[3] = f2tf(odd ? v31 : v30);   // (r0+8, c+4)
            int k0i = t * 8 + c4;
            #pragma unroll
            for (int nt = 0; nt < 8; nt++) {
                int dcol = nt * 8 + g;
                uint32_t bb[2] = { f2tf(vb[k0i * VST + dcol]),
                                   f2tf(vb[(k0i + 4) * VST + dcol]) };
                mma8(accO[nt], a, bb);
            }
        }

        if (kt < ktmax) CPWAITALL();
        __syncthreads();
    }

    // ---- epilogue ----
    float il0 = 1.f / l0, il1 = 1.f / l1;
    size_t ob0 = ((size_t)(b * Sl + qt * 128 + r0) * Hn + h) * 64;
    size_t ob1 = ((size_t)(b * Sl + qt * 128 + r0 + 8) * Hn + h) * 64;
    #pragma unroll
    for (int nt = 0; nt < 8; nt++) {
        int dcol = nt * 8 + 2 * c4;
        *(float2*)&o[ob0 + dcol] = make_float2(accO[nt][0] * il0, accO[nt][1] * il0);
        *(float2*)&o[ob1 + dcol] = make_float2(accO[nt][2] * il1, accO[nt][3] * il1);
    }
}

// ---------------------------------------------------------------------------
// Chunked delta-rule memory scan (side stream).
// ---------------------------------------------------------------------------
__global__ void memscan_kernel(const float* __restrict__ z,
                               const float* __restrict__ M_init,
                               const float* __restrict__ w_eta, const float* __restrict__ b_eta,
                               const float* __restrict__ w_alpha, const float* __restrict__ b_alpha,
                               const float* __restrict__ w_gate, const float* __restrict__ b_gate,
                               float* __restrict__ mem_out) {
    __shared__ float Ms[64][64];
    __shared__ float chs[64][64];
    __shared__ float red2[16][64];
    __shared__ float se[64], sa[64], sg[64], nrm[64];
    __shared__ float kmean[64], vt[64], diffv[64];
    __shared__ float red[256];
    __shared__ float sc_eta, sc_alpha, sc_gate, sc_scale;

    int b = blockIdx.x;
    int tid = threadIdx.x;
    int tx = tid & 15, ty = tid >> 4;

    #pragma unroll
    for (int i = 0; i < 16; i++) {
        int idx = tid + i * 256;
        Ms[idx >> 6][idx & 63] = M_init[idx];
    }
    __syncthreads();

    for (int c = 0; c < NCH; c++) {
        #pragma unroll
        for (int i = 0; i < 16; i++) {
            int idx = tid + i * 256;
            chs[idx >> 6][idx & 63] = z[((size_t)b * Sl + c * 64 + (idx >> 6)) * 64 + (idx & 63)];
        }
        __syncthreads();

        float o4[4][4] = {};
        #pragma unroll
        for (int d = 0; d < 64; d++) {
            float a0 = chs[ty*4+0][d], a1 = chs[ty*4+1][d];
            float a2 = chs[ty*4+2][d], a3 = chs[ty*4+3][d];
            float m0 = Ms[tx*4+0][d], m1 = Ms[tx*4+1][d];
            float m2 = Ms[tx*4+2][d], m3 = Ms[tx*4+3][d];
            o4[0][0] += a0*m0; o4[0][1] += a0*m1; o4[0][2] += a0*m2; o4[0][3] += a0*m3;
            o4[1][0] += a1*m0; o4[1][1] += a1*m1; o4[1][2] += a1*m2; o4[1][3] += a1*m3;
            o4[2][0] += a2*m0; o4[2][1] += a2*m1; o4[2][2] += a2*m2; o4[2][3] += a2*m3;
            o4[3][0] += a3*m0; o4[3][1] += a3*m1; o4[3][2] += a3*m2; o4[3][3] += a3*m3;
        }
        #pragma unroll
        for (int i = 0; i < 4; i++)
            #pragma unroll
            for (int j = 0; j < 4; j++)
                mem_out[((size_t)b * Sl + c * 64 + ty * 4 + i) * 64 + tx * 4 + j] = o4[i][j];
        #pragma unroll
        for (int j = 0; j < 4; j++)
            red2[ty][tx * 4 + j] = o4[0][j] + o4[1][j] + o4[2][j] + o4[3][j];
        __syncthreads();

        if (tid < 64) {
            float de = 0.f, da = 0.f, dg = 0.f, nn = 0.f;
            #pragma unroll
            for (int d = 0; d < 64; d++) {
                float x = chs[tid][d];
                de += x * w_eta[d];
                da += x * w_alpha[d];
                dg += x * w_gate[d];
                nn += x * x;
            }
            se[tid] = 0.2f / (1.f + expf(-(de + b_eta[0])));
            sa[tid] = 0.5f + 0.5f / (1.f + expf(-(da + b_alpha[0])));
            sg[tid] = 1.f / (1.f + expf(-(dg + b_gate[0])));
            nrm[tid] = fmaxf(sqrtf(nn), 1e-6f);
        }
        __syncthreads();

        if (tid < 64) {
            float s = 0.f;
            #pragma unroll
            for (int t = 0; t < 64; t++) s += chs[t][tid] / nrm[t];
            kmean[tid] = s * (1.f / 64.f);
        } else if (tid < 128) {
            int vv = tid - 64;
            float s = 0.f;
            #pragma unroll
            for (int yy = 0; yy < 16; yy++) s += red2[yy][vv];
            vt[vv] = s * (1.f / 64.f);
        } else if (tid == 128) {
            float e = 0.f, a = 0.f, gg = 0.f;
            #pragma unroll
            for (int t = 0; t < 64; t++) { e += se[t]; a += sa[t]; gg += sg[t]; }
            sc_eta = e * (1.f / 64.f);
            sc_alpha = a * (1.f / 64.f);
            sc_gate = gg * (1.f / 64.f);
        }
        __syncthreads();

        if (tid < 64) {
            float s = 0.f;
            #pragma unroll
            for (int d = 0; d < 64; d++) s += Ms[tid][d] * kmean[d];
            diffv[tid] = vt[tid] - s;
        }
        __syncthreads();

        float eg = sc_eta * sc_gate, al = sc_alpha;
        float ss2 = 0.f;
        #pragma unroll
        for (int i = 0; i < 16; i++) {
            int idx = tid + i * 256;
            int vv = idx >> 6, d = idx & 63;
            float mn = al * Ms[vv][d] + eg * diffv[vv] * kmean[d];
            Ms[vv][d] = mn;
            ss2 += mn * mn;
        }
        red[tid] = ss2;
        __syncthreads();
        for (int st = 128; st > 0; st >>= 1) {
            if (tid < st) red[tid] += red[tid + st];
            __syncthreads();
        }
        if (tid == 0) {
            float fro = sqrtf(red[0]);
            sc_scale = fminf(1.f, 30.f / fmaxf(fro, 1e-6f));
        }
        __syncthreads();
        #pragma unroll
        for (int i = 0; i < 16; i++) {
            int idx = tid + i * 256;
            Ms[idx >> 6][idx & 63] *= sc_scale;
        }
        __syncthreads();
    }
}

// ---------------------------------------------------------------------------
extern "C" void kernel_launch(void* const* d_in, const int* in_sizes, int n_in,
                              void* d_out, int out_size) {
    const float* x       = (const float*)d_in[0];
    const float* Wq      = (const float*)d_in[1];
    const float* Wk      = (const float*)d_in[2];
    const float* Wv      = (const float*)d_in[3];
    const float* Wo      = (const float*)d_in[4];
    const float* Wmemin  = (const float*)d_in[5];
    const float* Wmemout = (const float*)d_in[6];
    const float* M_init  = (const float*)d_in[7];
    const float* w_eta   = (const float*)d_in[8];
    const float* b_eta   = (const float*)d_in[9];
    const float* w_alpha = (const float*)d_in[10];
    const float* b_alpha = (const float*)d_in[11];
    const float* w_gate  = (const float*)d_in[12];
    const float* b_gate  = (const float*)d_in[13];
    float* out = (float*)d_out;

    float *q, *k, *v, *attn, *z, *mem;
    cudaGetSymbolAddress((void**)&q, g_q);
    cudaGetSymbolAddress((void**)&k, g_k);
    cudaGetSymbolAddress((void**)&v, g_v);
    cudaGetSymbolAddress((void**)&attn, g_attn);
    cudaGetSymbolAddress((void**)&z, g_z);
    cudaGetSymbolAddress((void**)&mem, g_mem);

    static cudaStream_t s2 = nullptr;
    static cudaEvent_t evZ = nullptr, evM = nullptr;
    static int inited = 0;
    if (!inited) {
        cudaStreamCreateWithFlags(&s2, cudaStreamNonBlocking);
        cudaEventCreateWithFlags(&evZ, cudaEventDisableTiming);
        cudaEventCreateWithFlags(&evM, cudaEventDisableTiming);
        cudaFuncSetAttribute(attn_kernel,
                             cudaFuncAttributeMaxDynamicSharedMemorySize, ATTN_BYTES);
        inited = 1;
    }

    // Fused projections (q, k, v, z)
    proj_kernel<<<dim3(25, 32), 256>>>(x, Wq, Wk, Wv, Wmemin, q, k, v, z);

    // Fork serial memscan onto side stream (depends on z)
    cudaEventRecord(evZ, 0);
    cudaStreamWaitEvent(s2, evZ, 0);
    memscan_kernel<<<Bsz, 256, 0, s2>>>(z, M_init, w_eta, b_eta, w_alpha, b_alpha,
                                        w_gate, b_gate, mem);
    cudaEventRecord(evM, s2);

    // RoPE
    rope_kernel<<<(Bsz*Sl*Hn*32 + 255)/256, 256>>>(q, Hn);
    rope_kernel<<<(Bsz*Sl*HKn*32 + 255)/256, 256>>>(k, HKn);

    // Attention
    attn_kernel<<<dim3(Sl/128, Bsz*Hn), 256, ATTN_BYTES>>>(q, k, v, attn);

    // Join memscan, then fused output GEMM
    cudaStreamWaitEvent((cudaStream_t)0, evM, 0);
    dual_gemm_kernel<<<dim3(16, 32), 256>>>(attn, Wo, Hn*HDn,
                                            mem, Wmemout, DVn, out, Dm);
}

// round 6
// speedup vs baseline: 4.0590x; 1.5146x over previous
#include <cuda_runtime.h>
#include <math.h>
#include <stdint.h>

#define Bsz 2
#define Sl  2048
#define Dm  1024
#define Hn  16
#define HKn 4
#define HDn 64
#define DKn 64
#define DVn 64
#define NCH 32
#define MS  (Bsz*Sl)

__device__ float g_q[Bsz*Sl*Hn*HDn];
__device__ float g_k[Bsz*Sl*HKn*HDn];
__device__ float g_v[Bsz*Sl*HKn*HDn];
__device__ float g_attn[Bsz*Sl*Hn*HDn];
__device__ float g_z[Bsz*Sl*DKn];
__device__ float g_mem[Bsz*Sl*DVn];

__device__ __forceinline__ uint32_t f2tf(float x) {
    uint32_t u; asm("cvt.rna.tf32.f32 %0, %1;" : "=r"(u) : "f"(x)); return u;
}

__device__ __forceinline__ unsigned su32(const void* p) {
    unsigned a;
    asm("{.reg .u64 t; cvta.to.shared.u64 t, %1; cvt.u32.u64 %0, t;}" : "=r"(a) : "l"(p));
    return a;
}
#define CP16(dst, src) asm volatile("cp.async.ca.shared.global [%0], [%1], 16;" :: "r"(dst), "l"(src))
#define CPCOMMIT()     asm volatile("cp.async.commit_group;")
#define CPWAITALL()    asm volatile("cp.async.wait_group 0;")

// mma.sync m16n8k8 tf32: D += A(16x8,row) * B(8x8,col)
__device__ __forceinline__ void mma8(float d[4], const uint32_t a[4], const uint32_t b[2]) {
    asm volatile(
        "mma.sync.aligned.m16n8k8.row.col.f32.tf32.tf32.f32 "
        "{%0,%1,%2,%3}, {%4,%5,%6,%7}, {%8,%9}, {%0,%1,%2,%3};"
        : "+f"(d[0]), "+f"(d[1]), "+f"(d[2]), "+f"(d[3])
        : "r"(a[0]), "r"(a[1]), "r"(a[2]), "r"(a[3]), "r"(b[0]), "r"(b[1]));
}

// ===========================================================================
// TF32 GEMM core: BM=128, BN=64, BK=16, 256 threads (8 warps, 4x2 warp grid),
// warp tile 32x32. Double-buffered smem, 1 sync per BK step.
// ===========================================================================
#define AS_STR 136
#define BS_STR 72

__device__ __forceinline__ void g_load(const float* __restrict__ A,
                                       const float* __restrict__ B,
                                       int K, int N, int row0, int col0, int k0,
                                       int tid, float4 ar[2], float4& br) {
    #pragma unroll
    for (int i = 0; i < 2; i++) {
        int vec = tid + i * 256;
        int m = vec >> 2, kq = vec & 3;
        ar[i] = *(const float4*)&A[(size_t)(row0 + m) * K + k0 + kq * 4];
    }
    int kk = tid >> 4, nq = tid & 15;
    br = *(const float4*)&B[(size_t)(k0 + kk) * N + col0 + nq * 4];
}

__device__ __forceinline__ void g_sts(uint32_t* As, uint32_t* Bs, int tid,
                                      const float4 ar[2], const float4& br) {
    #pragma unroll
    for (int i = 0; i < 2; i++) {
        int vec = tid + i * 256;
        int m = vec >> 2, kq = vec & 3;
        As[(kq * 4 + 0) * AS_STR + m] = f2tf(ar[i].x);
        As[(kq * 4 + 1) * AS_STR + m] = f2tf(ar[i].y);
        As[(kq * 4 + 2) * AS_STR + m] = f2tf(ar[i].z);
        As[(kq * 4 + 3) * AS_STR + m] = f2tf(ar[i].w);
    }
    int kk = tid >> 4, nq = tid & 15;
    uint4 t;
    t.x = f2tf(br.x); t.y = f2tf(br.y); t.z = f2tf(br.z); t.w = f2tf(br.w);
    *(uint4*)&Bs[kk * BS_STR + nq * 4] = t;
}

__device__ __forceinline__ void g_mma(const uint32_t* As, const uint32_t* Bs,
                                      int lane, int wm, int wn, float d[2][4][4]) {
    #pragma unroll
    for (int ks = 0; ks < 16; ks += 8) {
        int kc = ks + (lane & 3);
        uint32_t a[2][4], b[4][2];
        #pragma unroll
        for (int mt = 0; mt < 2; mt++) {
            int r = wm * 32 + mt * 16 + (lane >> 2);
            a[mt][0] = As[kc * AS_STR + r];
            a[mt][1] = As[kc * AS_STR + r + 8];
            a[mt][2] = As[(kc + 4) * AS_STR + r];
            a[mt][3] = As[(kc + 4) * AS_STR + r + 8];
        }
        #pragma unroll
        for (int nt = 0; nt < 4; nt++) {
            int n = wn * 32 + nt * 8 + (lane >> 2);
            b[nt][0] = Bs[kc * BS_STR + n];
            b[nt][1] = Bs[(kc + 4) * BS_STR + n];
        }
        #pragma unroll
        for (int mt = 0; mt < 2; mt++)
            #pragma unroll
            for (int nt = 0; nt < 4; nt++)
                mma8(d[mt][nt], a[mt], b[nt]);
    }
}

__device__ __forceinline__ void g_epilogue(float d[2][4][4], float* __restrict__ C,
                                           int N, int row0, int col0,
                                           int lane, int wm, int wn) {
    #pragma unroll
    for (int mt = 0; mt < 2; mt++) {
        #pragma unroll
        for (int nt = 0; nt < 4; nt++) {
            int r = row0 + wm * 32 + mt * 16 + (lane >> 2);
            int cc = col0 + wn * 32 + nt * 8 + 2 * (lane & 3);
            *(float2*)&C[(size_t)r * N + cc]       = make_float2(d[mt][nt][0], d[mt][nt][1]);
            *(float2*)&C[(size_t)(r + 8) * N + cc] = make_float2(d[mt][nt][2], d[mt][nt][3]);
        }
    }
}

// ---------------------------------------------------------------------------
// Fused projection GEMM: x @ {Wq|Wk|Wv|Wmemin}. grid=(25,32), block=256.
// ---------------------------------------------------------------------------
__global__ __launch_bounds__(256)
void proj_kernel(const float* __restrict__ x,
                 const float* __restrict__ Wq, const float* __restrict__ Wk,
                 const float* __restrict__ Wv, const float* __restrict__ Wz,
                 float* __restrict__ q, float* __restrict__ kout,
                 float* __restrict__ vout, float* __restrict__ z) {
    __shared__ uint32_t As[2][16 * AS_STR];
    __shared__ uint32_t Bs[2][16 * BS_STR];
    int tid = threadIdx.x;
    int lane = tid & 31, warp = tid >> 5;
    int wm = warp >> 1, wn = warp & 1;
    int ct = blockIdx.x;
    int row0 = blockIdx.y * 128;
    const float* B; float* C; int N, col0;
    if (ct < 16)      { B = Wq; C = q;    N = 1024; col0 = ct * 64; }
    else if (ct < 20) { B = Wk; C = kout; N = 256;  col0 = (ct - 16) * 64; }
    else if (ct < 24) { B = Wv; C = vout; N = 256;  col0 = (ct - 20) * 64; }
    else              { B = Wz; C = z;    N = 64;   col0 = 0; }

    float d[2][4][4] = {};
    float4 ar[2]; float4 br;
    g_load(x, B, 1024, N, row0, col0, 0, tid, ar, br);
    g_sts(As[0], Bs[0], tid, ar, br);
    __syncthreads();
    for (int k0 = 0; k0 < 1024; k0 += 16) {
        int cur = (k0 >> 4) & 1;
        if (k0 + 16 < 1024) g_load(x, B, 1024, N, row0, col0, k0 + 16, tid, ar, br);
        g_mma(As[cur], Bs[cur], lane, wm, wn, d);
        if (k0 + 16 < 1024) g_sts(As[cur ^ 1], Bs[cur ^ 1], tid, ar, br);
        __syncthreads();
    }
    g_epilogue(d, C, N, row0, col0, lane, wm, wn);
}

// ---------------------------------------------------------------------------
// Dual GEMM: C = A1@B1 + A2@B2. grid=(16,32), block=256.
// ---------------------------------------------------------------------------
__global__ __launch_bounds__(256)
void dual_gemm_kernel(const float* __restrict__ A1, const float* __restrict__ B1, int K1,
                      const float* __restrict__ A2, const float* __restrict__ B2, int K2,
                      float* __restrict__ C, int N) {
    __shared__ uint32_t As[2][16 * AS_STR];
    __shared__ uint32_t Bs[2][16 * BS_STR];
    int tid = threadIdx.x;
    int lane = tid & 31, warp = tid >> 5;
    int wm = warp >> 1, wn = warp & 1;
    int row0 = blockIdx.y * 128, col0 = blockIdx.x * 64;
    float d[2][4][4] = {};
    float4 ar[2]; float4 br;
    #pragma unroll
    for (int ph = 0; ph < 2; ph++) {
        const float* A = ph ? A2 : A1;
        const float* B = ph ? B2 : B1;
        int K = ph ? K2 : K1;
        g_load(A, B, K, N, row0, col0, 0, tid, ar, br);
        g_sts(As[0], Bs[0], tid, ar, br);
        __syncthreads();
        for (int k0 = 0; k0 < K; k0 += 16) {
            int cur = (k0 >> 4) & 1;
            if (k0 + 16 < K) g_load(A, B, K, N, row0, col0, k0 + 16, tid, ar, br);
            g_mma(As[cur], Bs[cur], lane, wm, wn, d);
            if (k0 + 16 < K) g_sts(As[cur ^ 1], Bs[cur ^ 1], tid, ar, br);
            __syncthreads();
        }
    }
    g_epilogue(d, C, N, row0, col0, lane, wm, wn);
}

// ---------------------------------------------------------------------------
// Merged RoPE: q (16 heads) then k (4 heads), in place.
// ---------------------------------------------------------------------------
__global__ void rope_kernel(float* __restrict__ qp, float* __restrict__ kp) {
    int idx = blockIdx.x * blockDim.x + threadIdx.x;
    const int qtot = Bsz * Sl * Hn * 32;
    const int ktot = Bsz * Sl * HKn * 32;
    float* t; int nheads;
    if (idx < qtot) { t = qp; nheads = Hn; }
    else { idx -= qtot; if (idx >= ktot) return; t = kp; nheads = HKn; }
    int j = idx & 31;
    int h = (idx >> 5) % nheads;
    int s = ((idx >> 5) / nheads) % Sl;
    int b = idx / (32 * nheads * Sl);
    float inv = powf(500000.0f, -(float)(2 * j) / 64.0f);
    float ang = (float)s * inv;
    float c, sn;
    __sincosf(ang, &sn, &c);
    size_t base = ((size_t)(b * Sl + s) * nheads + h) * 64;
    float u1 = t[base + j], u2 = t[base + j + 32];
    t[base + j]      = u1 * c - u2 * sn;
    t[base + j + 32] = u2 * c + u1 * sn;
}

// ---------------------------------------------------------------------------
// TF32 flash attention: 128q x 64kv tiles, 256 threads (8 warps x 16 rows).
// kv processed as two 32-col sub-tiles (halves register pressure -> real
// 2 CTA/SM). Softmax in log2 domain: scale = 0.125*log2(e) folded into Q,
// bare exp2f (EX2, no FMUL). K/V double-buffered raw via cp.async.
// ---------------------------------------------------------------------------
#define QST 68
#define KST 68
#define VST 72
#define ATTN_WORDS (128*QST + 2*64*KST + 2*64*VST)
#define ATTN_BYTES (ATTN_WORDS * 4)
#define QSCALE 0.18033688f   // 0.125 * log2(e)

__global__ __launch_bounds__(256, 2)
void attn_kernel(const float* __restrict__ q, const float* __restrict__ k,
                 const float* __restrict__ v, float* __restrict__ o) {
    extern __shared__ float smf[];
    uint32_t* qs = (uint32_t*)smf;          // [r:128][d:64] tf32, stride 68
    float* ks = smf + 128 * QST;            // 2 x [c:64][d:64] raw, stride 68
    float* vs = ks + 2 * 64 * KST;          // 2 x [c:64][d:64] raw, stride 72

    int qt = (int)gridDim.x - 1 - (int)blockIdx.x;   // longest tiles first
    int bh = blockIdx.y;
    int b = bh >> 4, h = bh & 15, kh = h >> 2;
    int tid = threadIdx.x;
    int lane = tid & 31, w = tid >> 5;
    int g = lane >> 2, c4 = lane & 3;
    int r0 = w * 16 + g;

    // ---- load Q tile (scaled into log2 domain, tf32) ----
    size_t qbase = ((size_t)(b * Sl + qt * 128) * Hn + h) * 64;
    #pragma unroll
    for (int i = 0; i < 8; i++) {
        int vec = tid + i * 256;
        int r = vec >> 4, dq = vec & 15;
        float4 t = *(const float4*)&q[qbase + (size_t)r * Hn * 64 + dq * 4];
        uint4 u;
        u.x = f2tf(t.x * QSCALE); u.y = f2tf(t.y * QSCALE);
        u.z = f2tf(t.z * QSCALE); u.w = f2tf(t.w * QSCALE);
        *(uint4*)&qs[r * QST + dq * 4] = u;
    }

    size_t kvbase = ((size_t)(b * Sl) * HKn + kh) * 64;
    int ktmax = 2 * qt + 1;

    // ---- prologue: cp.async K0,V0 into buffer 0 ----
    {
        unsigned kd = su32(ks), vd = su32(vs);
        #pragma unroll
        for (int i = 0; i < 4; i++) {
            int vec = tid + i * 256;
            int c = vec >> 4, dq = vec & 15;
            CP16(kd + (unsigned)((c * KST + dq * 4) * 4),
                 &k[kvbase + (size_t)c * HKn * 64 + dq * 4]);
            CP16(vd + (unsigned)((c * VST + dq * 4) * 4),
                 &v[kvbase + (size_t)c * HKn * 64 + dq * 4]);
        }
        CPCOMMIT();
    }

    float m0 = -1e30f, m1 = -1e30f, l0 = 0.f, l1 = 0.f;
    float accO[8][4] = {};
    CPWAITALL();
    __syncthreads();

    for (int kt = 0; kt <= ktmax; kt++) {
        const float* kb = ks + (kt & 1) * 64 * KST;
        const float* vb = vs + (kt & 1) * 64 * VST;

        // issue next K/V loads into the other buffer
        if (kt < ktmax) {
            unsigned kd = su32(ks + ((kt + 1) & 1) * 64 * KST);
            unsigned vd = su32(vs + ((kt + 1) & 1) * 64 * VST);
            size_t base = kvbase + (size_t)(kt + 1) * 64 * HKn * 64;
            #pragma unroll
            for (int i = 0; i < 4; i++) {
                int vec = tid + i * 256;
                int c = vec >> 4, dq = vec & 15;
                CP16(kd + (unsigned)((c * KST + dq * 4) * 4),
                     &k[base + (size_t)c * HKn * 64 + dq * 4]);
                CP16(vd + (unsigned)((c * VST + dq * 4) * 4),
                     &v[base + (size_t)c * HKn * 64 + dq * 4]);
            }
            CPCOMMIT();
        }

        bool diag = (kt >= 2 * qt);
        #pragma unroll
        for (int half = 0; half < 2; half++) {
            // ---- QK^T over this 32-col sub-tile ----
            float sc[4][4] = {};
            #pragma unroll
            for (int t8 = 0; t8 < 8; t8++) {
                int kc = t8 * 8 + c4;
                uint32_t a[4];
                a[0] = qs[r0 * QST + kc];
                a[1] = qs[(r0 + 8) * QST + kc];
                a[2] = qs[r0 * QST + kc + 4];
                a[3] = qs[(r0 + 8) * QST + kc + 4];
                #pragma unroll
                for (int nt = 0; nt < 4; nt++) {
                    int n = half * 32 + nt * 8 + g;
                    uint32_t bb[2] = { f2tf(kb[n * KST + kc]), f2tf(kb[n * KST + kc + 4]) };
                    mma8(sc[nt], a, bb);
                }
            }

            // ---- causal mask ----
            if (diag) {
                int rg0 = qt * 128 + r0, rg1 = rg0 + 8;
                #pragma unroll
                for (int nt = 0; nt < 4; nt++) {
                    int cg = kt * 64 + half * 32 + nt * 8 + 2 * c4;
                    if (cg > rg0)     sc[nt][0] = -1e30f;
                    if (cg + 1 > rg0) sc[nt][1] = -1e30f;
                    if (cg > rg1)     sc[nt][2] = -1e30f;
                    if (cg + 1 > rg1) sc[nt][3] = -1e30f;
                }
            }

            // ---- online softmax (log2 domain, bare EX2) ----
            float mx0 = m0, mx1 = m1;
            #pragma unroll
            for (int nt = 0; nt < 4; nt++) {
                mx0 = fmaxf(mx0, fmaxf(sc[nt][0], sc[nt][1]));
                mx1 = fmaxf(mx1, fmaxf(sc[nt][2], sc[nt][3]));
            }
            mx0 = fmaxf(mx0, __shfl_xor_sync(0xffffffffu, mx0, 1));
            mx0 = fmaxf(mx0, __shfl_xor_sync(0xffffffffu, mx0, 2));
            mx1 = fmaxf(mx1, __shfl_xor_sync(0xffffffffu, mx1, 1));
            mx1 = fmaxf(mx1, __shfl_xor_sync(0xffffffffu, mx1, 2));
            float f0 = exp2f(m0 - mx0), f1 = exp2f(m1 - mx1);
            m0 = mx0; m1 = mx1;
            float sum0 = 0.f, sum1 = 0.f;
            #pragma unroll
            for (int nt = 0; nt < 4; nt++) {
                sc[nt][0] = exp2f(sc[nt][0] - mx0); sum0 += sc[nt][0];
                sc[nt][1] = exp2f(sc[nt][1] - mx0); sum0 += sc[nt][1];
                sc[nt][2] = exp2f(sc[nt][2] - mx1); sum1 += sc[nt][2];
                sc[nt][3] = exp2f(sc[nt][3] - mx1); sum1 += sc[nt][3];
            }
            sum0 += __shfl_xor_sync(0xffffffffu, sum0, 1);
            sum0 += __shfl_xor_sync(0xffffffffu, sum0, 2);
            sum1 += __shfl_xor_sync(0xffffffffu, sum1, 1);
            sum1 += __shfl_xor_sync(0xffffffffu, sum1, 2);
            l0 = l0 * f0 + sum0;
            l1 = l1 * f1 + sum1;
            #pragma unroll
            for (int nt = 0; nt < 8; nt++) {
                accO[nt][0] *= f0; accO[nt][1] *= f0;
                accO[nt][2] *= f1; accO[nt][3] *= f1;
            }

            // ---- P @ V over this sub-tile's 32 kv rows ----
            int src0 = (lane & ~3) | (c4 >> 1);
            int src1 = src0 + 2;
            bool odd = c4 & 1;
            #pragma unroll
            for (int t = 0; t < 4; t++) {
                float v00 = __shfl_sync(0xffffffffu, sc[t][0], src0);
                float v01 = __shfl_sync(0xffffffffu, sc[t][1], src0);
                float v10 = __shfl_sync(0xffffffffu, sc[t][0], src1);
                float v11 = __shfl_sync(0xffffffffu, sc[t][1], src1);
                float v20 = __shfl_sync(0xffffffffu, sc[t][2], src0);
                float v21 = __shfl_sync(0xffffffffu, sc[t][3], src0);
                float v30 = __shfl_sync(0xffffffffu, sc[t][2], src1);
                float v31 = __shfl_sync(0xffffffffu, sc[t][3], src1);
                uint32_t a[4];
                a[0] = f2tf(odd ? v01 : v00);   // (r0,   c)
                a[1] = f2tf(odd ? v21 : v20);   // (r0+8, c)
                a[2] = f2tf(odd ? v11 : v10);   // (r0,   c+4)
                a[3] = f2tf(odd ? v31 : v30);   // (r0+8, c+4)
                int k0i = half * 32 + t * 8 + c4;
                #pragma unroll
                for (int nt = 0; nt < 8; nt++) {
                    int dcol = nt * 8 + g;
                    uint32_t bb[2] = { f2tf(vb[k0i * VST + dcol]),
                                       f2tf(vb[(k0i + 4) * VST + dcol]) };
                    mma8(accO[nt], a, bb);
                }
            }
        }

        if (kt < ktmax) CPWAITALL();
        __syncthreads();
    }

    // ---- epilogue ----
    float il0 = 1.f / l0, il1 = 1.f / l1;
    size_t ob0 = ((size_t)(b * Sl + qt * 128 + r0) * Hn + h) * 64;
    size_t ob1 = ((size_t)(b * Sl + qt * 128 + r0 + 8) * Hn + h) * 64;
    #pragma unroll
    for (int nt = 0; nt < 8; nt++) {
        int dcol = nt * 8 + 2 * c4;
        *(float2*)&o[ob0 + dcol] = make_float2(accO[nt][0] * il0, accO[nt][1] * il0);
        *(float2*)&o[ob1 + dcol] = make_float2(accO[nt][2] * il1, accO[nt][3] * il1);
    }
}

// ---------------------------------------------------------------------------
// Chunked delta-rule memory scan (side stream). Stride-65 smem (kills the
// 16-way Ms bank conflict), 4-thread/row shfl reductions, warp-level fro.
// ---------------------------------------------------------------------------
__global__ __launch_bounds__(256)
void memscan_kernel(const float* __restrict__ z,
                    const float* __restrict__ M_init,
                    const float* __restrict__ w_eta, const float* __restrict__ b_eta,
                    const float* __restrict__ w_alpha, const float* __restrict__ b_alpha,
                    const float* __restrict__ w_gate, const float* __restrict__ b_gate,
                    float* __restrict__ mem_out) {
    __shared__ float Ms[64][65];
    __shared__ float chs[64][65];
    __shared__ float red2[16][64];
    __shared__ float se[64], sa[64], sg[64], nrm[64];
    __shared__ float kmean[64], vt[64], diffv[64];
    __shared__ float swe[64], swa[64], swg[64];
    __shared__ float redw[8];
    __shared__ float sc_eta, sc_alpha, sc_gate, sc_scale;

    int b = blockIdx.x;
    int tid = threadIdx.x;
    int tx = tid & 15, ty = tid >> 4;
    int lane = tid & 31, warp = tid >> 5;
    int tok = tid >> 2, part = tid & 3;
    float be = b_eta[0], ba = b_alpha[0], bg = b_gate[0];

    if (tid < 64) { swe[tid] = w_eta[tid]; swa[tid] = w_alpha[tid]; swg[tid] = w_gate[tid]; }
    #pragma unroll
    for (int i = 0; i < 16; i++) {
        int idx = tid + i * 256;
        Ms[idx >> 6][idx & 63] = M_init[idx];
    }
    __syncthreads();

    for (int c = 0; c < NCH; c++) {
        #pragma unroll
        for (int i = 0; i < 16; i++) {
            int idx = tid + i * 256;
            chs[idx >> 6][idx & 63] = z[((size_t)b * Sl + c * 64 + (idx >> 6)) * 64 + (idx & 63)];
        }
        __syncthreads();

        // out[t][v] = sum_d ch[t][d] * M[v][d]
        float o4[4][4] = {};
        #pragma unroll
        for (int d = 0; d < 64; d++) {
            float a0 = chs[ty*4+0][d], a1 = chs[ty*4+1][d];
            float a2 = chs[ty*4+2][d], a3 = chs[ty*4+3][d];
            float m0 = Ms[tx*4+0][d], m1 = Ms[tx*4+1][d];
            float m2 = Ms[tx*4+2][d], m3 = Ms[tx*4+3][d];
            o4[0][0] += a0*m0; o4[0][1] += a0*m1; o4[0][2] += a0*m2; o4[0][3] += a0*m3;
            o4[1][0] += a1*m0; o4[1][1] += a1*m1; o4[1][2] += a1*m2; o4[1][3] += a1*m3;
            o4[2][0] += a2*m0; o4[2][1] += a2*m1; o4[2][2] += a2*m2; o4[2][3] += a2*m3;
            o4[3][0] += a3*m0; o4[3][1] += a3*m1; o4[3][2] += a3*m2; o4[3][3] += a3*m3;
        }
        #pragma unroll
        for (int i = 0; i < 4; i++)
            #pragma unroll
            for (int j = 0; j < 4; j++)
                mem_out[((size_t)b * Sl + c * 64 + ty * 4 + i) * 64 + tx * 4 + j] = o4[i][j];
        #pragma unroll
        for (int j = 0; j < 4; j++)
            red2[ty][tx * 4 + j] = o4[0][j] + o4[1][j] + o4[2][j] + o4[3][j];
        __syncthreads();

        // gates + norm: 4 threads per token
        {
            float de = 0.f, da = 0.f, dg = 0.f, nn = 0.f;
            int d0 = part * 16;
            #pragma unroll
            for (int dd = 0; dd < 16; dd++) {
                float xv = chs[tok][d0 + dd];
                de = fmaf(xv, swe[d0 + dd], de);
                da = fmaf(xv, swa[d0 + dd], da);
                dg = fmaf(xv, swg[d0 + dd], dg);
                nn = fmaf(xv, xv, nn);
            }
            de += __shfl_xor_sync(0xffffffffu, de, 1); de += __shfl_xor_sync(0xffffffffu, de, 2);
            da += __shfl_xor_sync(0xffffffffu, da, 1); da += __shfl_xor_sync(0xffffffffu, da, 2);
            dg += __shfl_xor_sync(0xffffffffu, dg, 1); dg += __shfl_xor_sync(0xffffffffu, dg, 2);
            nn += __shfl_xor_sync(0xffffffffu, nn, 1); nn += __shfl_xor_sync(0xffffffffu, nn, 2);
            if (part == 0) {
                se[tok] = 0.2f / (1.f + __expf(-(de + be)));
                sa[tok] = 0.5f + 0.5f / (1.f + __expf(-(da + ba)));
                sg[tok] = 1.f / (1.f + __expf(-(dg + bg)));
                nrm[tok] = fmaxf(sqrtf(nn), 1e-6f);
            }
        }
        __syncthreads();

        // kmean + vt: 4 threads per column
        {
            float s = 0.f, s2 = 0.f;
            #pragma unroll
            for (int t = 0; t < 16; t++) s += chs[part * 16 + t][tok] / nrm[part * 16 + t];
            #pragma unroll
            for (int yy = 0; yy < 4; yy++) s2 += red2[part * 4 + yy][tok];
            s  += __shfl_xor_sync(0xffffffffu, s, 1);  s  += __shfl_xor_sync(0xffffffffu, s, 2);
            s2 += __shfl_xor_sync(0xffffffffu, s2, 1); s2 += __shfl_xor_sync(0xffffffffu, s2, 2);
            if (part == 0) { kmean[tok] = s * (1.f / 64.f); vt[tok] = s2 * (1.f / 64.f); }
        }
        __syncthreads();

        // scalar means (warp 0) + Mk dot (all threads)
        if (tid < 32) {
            float e = se[tid] + se[tid + 32];
            float a = sa[tid] + sa[tid + 32];
            float gg = sg[tid] + sg[tid + 32];
            #pragma unroll
            for (int st = 16; st; st >>= 1) {
                e  += __shfl_xor_sync(0xffffffffu, e, st);
                a  += __shfl_xor_sync(0xffffffffu, a, st);
                gg += __shfl_xor_sync(0xffffffffu, gg, st);
            }
            if (tid == 0) {
                sc_eta = e * (1.f / 64.f);
                sc_alpha = a * (1.f / 64.f);
                sc_gate = gg * (1.f / 64.f);
            }
        }
        {
            float s = 0.f;
            int d0 = part * 16;
            #pragma unroll
            for (int dd = 0; dd < 16; dd++)
                s = fmaf(Ms[tok][d0 + dd], kmean[d0 + dd], s);
            s += __shfl_xor_sync(0xffffffffu, s, 1);
            s += __shfl_xor_sync(0xffffffffu, s, 2);
            if (part == 0) diffv[tok] = vt[tok] - s;
        }
        __syncthreads();

        // M update + Frobenius norm
        float eg = sc_eta * sc_gate, al = sc_alpha;
        float ss2 = 0.f;
        #pragma unroll
        for (int i = 0; i < 16; i++) {
            int idx = tid + i * 256;
            int vv = idx >> 6, d = idx & 63;
            float mn = al * Ms[vv][d] + eg * diffv[vv] * kmean[d];
            Ms[vv][d] = mn;
            ss2 = fmaf(mn, mn, ss2);
        }
        #pragma unroll
        for (int st = 16; st; st >>= 1) ss2 += __shfl_xor_sync(0xffffffffu, ss2, st);
        if (lane == 0) redw[warp] = ss2;
        __syncthreads();
        if (tid == 0) {
            float fro = sqrtf(redw[0] + redw[1] + redw[2] + redw[3] +
                              redw[4] + redw[5] + redw[6] + redw[7]);
            sc_scale = fminf(1.f, 30.f / fmaxf(fro, 1e-6f));
        }
        __syncthreads();
        #pragma unroll
        for (int i = 0; i < 16; i++) {
            int idx = tid + i * 256;
            Ms[idx >> 6][idx & 63] *= sc_scale;
        }
        __syncthreads();
    }
}

// ---------------------------------------------------------------------------
extern "C" void kernel_launch(void* const* d_in, const int* in_sizes, int n_in,
                              void* d_out, int out_size) {
    const float* x       = (const float*)d_in[0];
    const float* Wq      = (const float*)d_in[1];
    const float* Wk      = (const float*)d_in[2];
    const float* Wv      = (const float*)d_in[3];
    const float* Wo      = (const float*)d_in[4];
    const float* Wmemin  = (const float*)d_in[5];
    const float* Wmemout = (const float*)d_in[6];
    const float* M_init  = (const float*)d_in[7];
    const float* w_eta   = (const float*)d_in[8];
    const float* b_eta   = (const float*)d_in[9];
    const float* w_alpha = (const float*)d_in[10];
    const float* b_alpha = (const float*)d_in[11];
    const float* w_gate  = (const float*)d_in[12];
    const float* b_gate  = (const float*)d_in[13];
    float* out = (float*)d_out;

    float *q, *k, *v, *attn, *z, *mem;
    cudaGetSymbolAddress((void**)&q, g_q);
    cudaGetSymbolAddress((void**)&k, g_k);
    cudaGetSymbolAddress((void**)&v, g_v);
    cudaGetSymbolAddress((void**)&attn, g_attn);
    cudaGetSymbolAddress((void**)&z, g_z);
    cudaGetSymbolAddress((void**)&mem, g_mem);

    static cudaStream_t s2 = nullptr;
    static cudaEvent_t evZ = nullptr, evM = nullptr;
    static int inited = 0;
    if (!inited) {
        cudaStreamCreateWithFlags(&s2, cudaStreamNonBlocking);
        cudaEventCreateWithFlags(&evZ, cudaEventDisableTiming);
        cudaEventCreateWithFlags(&evM, cudaEventDisableTiming);
        cudaFuncSetAttribute(attn_kernel,
                             cudaFuncAttributeMaxDynamicSharedMemorySize, ATTN_BYTES);
        inited = 1;
    }

    // Fused projections (q, k, v, z)
    proj_kernel<<<dim3(25, 32), 256>>>(x, Wq, Wk, Wv, Wmemin, q, k, v, z);

    // Fork serial memscan onto side stream (depends on z)
    cudaEventRecord(evZ, 0);
    cudaStreamWaitEvent(s2, evZ, 0);
    memscan_kernel<<<Bsz, 256, 0, s2>>>(z, M_init, w_eta, b_eta, w_alpha, b_alpha,
                                        w_gate, b_gate, mem);
    cudaEventRecord(evM, s2);

    // RoPE (merged q+k)
    {
        int total = Bsz * Sl * (Hn + HKn) * 32;
        rope_kernel<<<(total + 255) / 256, 256>>>(q, k);
    }

    // Attention
    attn_kernel<<<dim3(Sl/128, Bsz*Hn), 256, ATTN_BYTES>>>(q, k, v, attn);

    // Join memscan, then fused output GEMM
    cudaStreamWaitEvent((cudaStream_t)0, evM, 0);
    dual_gemm_kernel<<<dim3(16, 32), 256>>>(attn, Wo, Hn*HDn,
                                            mem, Wmemout, DVn, out, Dm);
}